// round 3
// baseline (speedup 1.0000x reference)
#include <cuda_runtime.h>
#include <math.h>

#define BB 4
#define NN 20480
#define KK 16
#define NPTS (BB*NN)

// Scratch (static device globals — no allocation in kernel_launch)
__device__ float g_feat0[NPTS*16];     // relu(m1) features, point-major [p][c]
__device__ float g_feat1[NPTS*16];     // after pool1+p1m
__device__ float g_feat2[NPTS*32];     // after pool2+p2m
__device__ float g_lrep2[NPTS*KK*16];  // [(p*K+k)][c]
__device__ float g_gdis[NPTS*KK];      // exp(-r_dis)
__device__ float g_lg[NPTS];           // local/global volume ratio

// ---------- fast math on the FMA pipe (avoid MUFU saturation) ----------
__device__ __forceinline__ float fexp(float x){
    // e^x via 2^(x*log2e), round-to-nearest-int range reduction, deg-5 Taylor.
    x = fminf(fmaxf(x, -87.0f), 87.0f);
    const float L2E = 1.4426950408889634f;
    float z  = fmaf(x, L2E, 12582912.0f);      // magic = 1.5*2^23
    float nf = z - 12582912.0f;                // nearest int as float
    float f  = fmaf(x, L2E, -nf);              // fractional part in [-0.5,0.5]
    float p  = fmaf(f, 1.3333558147e-3f, 9.6181291076e-3f);
    p = fmaf(f, p, 5.5504108664e-2f);
    p = fmaf(f, p, 2.4022650696e-1f);
    p = fmaf(f, p, 6.9314718056e-1f);
    p = fmaf(f, p, 1.0f);
    int e = (__float_as_int(z) << 23) + 0x3F800000; // 2^n bits
    return p * __int_as_float(e);
}

__device__ __forceinline__ float fatan2(float y, float x){
    float ax = fabsf(x), ay = fabsf(y);
    float mx = fmaxf(ax, ay), mn = fminf(ax, ay);
    float a = (mx > 0.0f) ? __fdividef(mn, mx) : 0.0f;  // atan2(0,0)=0 safe
    float s = a*a;
    float r = -0.0117212f;
    r = fmaf(r, s,  0.05265332f);
    r = fmaf(r, s, -0.11643287f);
    r = fmaf(r, s,  0.19354346f);
    r = fmaf(r, s, -0.33262347f);
    r = fmaf(r, s,  0.99997726f);
    r = r * a;
    if (ay > ax) r = 1.57079637f - r;
    if (x < 0.0f) r = 3.14159274f - r;
    if (y < 0.0f) r = -r;
    return r;
}

// half-warp (16-lane segment) reductions; all 32 lanes always active
__device__ __forceinline__ float rsum16(float v){
    v += __shfl_xor_sync(0xffffffffu, v, 1);
    v += __shfl_xor_sync(0xffffffffu, v, 2);
    v += __shfl_xor_sync(0xffffffffu, v, 4);
    v += __shfl_xor_sync(0xffffffffu, v, 8);
    return v;
}
__device__ __forceinline__ float rmax16(float v){
    v = fmaxf(v, __shfl_xor_sync(0xffffffffu, v, 1));
    v = fmaxf(v, __shfl_xor_sync(0xffffffffu, v, 2));
    v = fmaxf(v, __shfl_xor_sync(0xffffffffu, v, 4));
    v = fmaxf(v, __shfl_xor_sync(0xffffffffu, v, 8));
    return v;
}

// =================== Kernel A: feat0 = relu(g*(m1_W@feature)+b) ===================
__global__ __launch_bounds__(256) void kA(const float* __restrict__ feat,
                                          const float* __restrict__ W,
                                          const float* __restrict__ gg,
                                          const float* __restrict__ bb){
    __shared__ float sW[256], sg[16], sb[16];
    int tid = threadIdx.x;
    sW[tid] = W[tid];
    if (tid < 16){ sg[tid]=gg[tid]; sb[tid]=bb[tid]; }
    __syncthreads();
    int p = blockIdx.x*256 + tid;
    int b = p / NN, n = p - b*NN;
    float x[16];
#pragma unroll
    for (int c=0;c<16;c++) x[c] = feat[(b*16 + c)*NN + n];
    float y[16];
#pragma unroll
    for (int o=0;o<16;o++){
        float acc = 0.0f;
#pragma unroll
        for (int c=0;c<16;c++) acc = fmaf(sW[o*16+c], x[c], acc);
        y[o] = fmaxf(fmaf(sg[o], acc, sb[o]), 0.0f);
    }
    float4* dst = (float4*)(g_feat0 + p*16);
    dst[0] = make_float4(y[0],y[1],y[2],y[3]);
    dst[1] = make_float4(y[4],y[5],y[6],y[7]);
    dst[2] = make_float4(y[8],y[9],y[10],y[11]);
    dst[3] = make_float4(y[12],y[13],y[14],y[15]);
}

// =========== Kernel B: geometry + lrep + lrep2 + pool1 + p1m -> feat1 ===========
__global__ __launch_bounds__(256,2) void kB(const float* __restrict__ xyz,
                                            const int*   __restrict__ nidx,
    const float* __restrict__ lm1W, const float* __restrict__ lm1g, const float* __restrict__ lm1b,
    const float* __restrict__ lm2W, const float* __restrict__ lm2g, const float* __restrict__ lm2b,
    const float* __restrict__ fcW,
    const float* __restrict__ mW, const float* __restrict__ mg, const float* __restrict__ mb){
    __shared__ float s_lm1[16*12];
    __shared__ float s_lm1g[16], s_lm1b[16];
    __shared__ float s_lm2[16*16];
    __shared__ float s_lm2g[16], s_lm2b[16];
    __shared__ float s_fc[32*36];
    __shared__ float s_mT[32*16];      // transposed p1m: [in][out]
    __shared__ float s_mg[16], s_mb[16];
    int tid = threadIdx.x;
    for (int i = tid; i < 16*9; i += 256) s_lm1[(i/9)*12 + (i%9)] = lm1W[i];
    if (tid < 16){
        s_lm1g[tid]=lm1g[tid]; s_lm1b[tid]=lm1b[tid];
        s_lm2g[tid]=lm2g[tid]; s_lm2b[tid]=lm2b[tid];
        s_mg[tid]=mg[tid];     s_mb[tid]=mb[tid];
    }
    if (tid < 256) s_lm2[tid] = lm2W[tid];
    for (int i = tid; i < 32*34; i += 256) s_fc[(i/34)*36 + (i%34)] = fcW[i];
    for (int i = tid; i < 512; i += 256){ int o = i >> 5, c = i & 31; s_mT[c*16 + o] = mW[i]; }
    __syncthreads();

    int k = tid & 15, pg = tid >> 4;
    int p = blockIdx.x*16 + pg;
    int b = p / NN, n = p - b*NN;
    const float* xb = xyz + b*(NN*3);
    int idx = nidx[p*KK + k];
    float nx = xb[idx*3+0], ny = xb[idx*3+1], nz = xb[idx*3+2];
    float cx = xb[n*3+0],   cy = xb[n*3+1],   cz = xb[n*3+2];
    float rx = cx-nx, ry = cy-ny, rz = cz-nz;
    float dxy2 = fmaf(rx,rx, ry*ry);
    float rdis = sqrtf(dxy2 + rz*rz);
    float gdis = fexp(-rdis);
    float ralpha = fatan2(ry, rx);
    float rbeta  = fatan2(rz, sqrtf(dxy2));
    // mean neighbor position (over K=16 lanes)
    float mxn = rsum16(nx)*0.0625f;
    float myn = rsum16(ny)*0.0625f;
    float mzn = rsum16(nz)*0.0625f;
    float dx = cx - mxn, dy = cy - myn, dz = cz - mzn;
    float dalpha = fatan2(dy, dx);
    float dbeta  = fatan2(dz, sqrtf(fmaf(dx,dx,dy*dy)));
    // local/global volume ratio
    float mr = rmax16(rdis);
    if (k == 0){
        float cn = sqrtf(cx*cx + cy*cy + cz*cz);
        float lv = mr*mr*mr;
        float gv = cn*cn*cn;
        g_lg[p] = __fdividef(lv, gv);
    }
    g_gdis[p*KK + k] = gdis;

    float lr[9] = { ralpha - dalpha, rbeta - dbeta, rdis, cx, cy, cz, nx, ny, nz };

    float in34[34];
    in34[0] = gdis;
    // lrep = relu(lm1)
#pragma unroll
    for (int o=0;o<16;o++){
        float acc = 0.0f;
#pragma unroll
        for (int c=0;c<9;c++) acc = fmaf(s_lm1[o*12+c], lr[c], acc);
        in34[18+o] = fmaxf(fmaf(s_lm1g[o], acc, s_lm1b[o]), 0.0f);
    }
    // lrep2 = relu(lm2 @ lrep), store for pool2
    float l2v[16];
#pragma unroll
    for (int o=0;o<16;o++){
        float acc = 0.0f;
#pragma unroll
        for (int c=0;c<16;c++) acc = fmaf(s_lm2[o*16+c], in34[18+c], acc);
        l2v[o] = fmaxf(fmaf(s_lm2g[o], acc, s_lm2b[o]), 0.0f);
    }
    float4* ldst = (float4*)(g_lrep2 + (p*KK + k)*16);
    ldst[0] = make_float4(l2v[0],l2v[1],l2v[2],l2v[3]);
    ldst[1] = make_float4(l2v[4],l2v[5],l2v[6],l2v[7]);
    ldst[2] = make_float4(l2v[8],l2v[9],l2v[10],l2v[11]);
    ldst[3] = make_float4(l2v[12],l2v[13],l2v[14],l2v[15]);

    // gather neighbor features + feature distance
    const float4* fsrc = (const float4*)(g_feat0 + (b*NN + idx)*16);
    float4 q0 = fsrc[0], q1 = fsrc[1], q2 = fsrc[2], q3 = fsrc[3];
    in34[2]=q0.x;  in34[3]=q0.y;  in34[4]=q0.z;  in34[5]=q0.w;
    in34[6]=q1.x;  in34[7]=q1.y;  in34[8]=q1.z;  in34[9]=q1.w;
    in34[10]=q2.x; in34[11]=q2.y; in34[12]=q2.z; in34[13]=q2.w;
    in34[14]=q3.x; in34[15]=q3.y; in34[16]=q3.z; in34[17]=q3.w;
    const float4* csrc = (const float4*)(g_feat0 + p*16);
    float4 a0 = csrc[0], a1 = csrc[1], a2 = csrc[2], a3 = csrc[3];
    float sad = fabsf(a0.x-q0.x)+fabsf(a0.y-q0.y)+fabsf(a0.z-q0.z)+fabsf(a0.w-q0.w)
              + fabsf(a1.x-q1.x)+fabsf(a1.y-q1.y)+fabsf(a1.z-q1.z)+fabsf(a1.w-q1.w)
              + fabsf(a2.x-q2.x)+fabsf(a2.y-q2.y)+fabsf(a2.z-q2.z)+fabsf(a2.w-q2.w)
              + fabsf(a3.x-q3.x)+fabsf(a3.y-q3.y)+fabsf(a3.z-q3.z)+fabsf(a3.w-q3.w);
    in34[1] = 2.0f * fexp(-sad * 0.0625f);   // LAMDA * f_dis

    // attentive pool: per output channel, softmax over K (cross-lane)
    float flcA = 0.0f, flcB = 0.0f;
#pragma unroll
    for (int o=0;o<32;o++){
        float l = 0.0f;
#pragma unroll
        for (int c=0;c<34;c++) l = fmaf(s_fc[o*36+c], in34[c], l);
        float e  = fexp(l);
        float nu = e * in34[2+o];
        float es = rsum16(e);
        float ns = rsum16(nu);
        float flc = __fdividef(ns, es);
        if (o == k)      flcA = flc;
        if (o == k + 16) flcB = flc;
    }
    // p1m: lane k computes output channel k (16 outs, 32 ins)
    float acc = 0.0f;
#pragma unroll
    for (int i=0;i<16;i++){
        float v = __shfl_sync(0xffffffffu, flcA, i, 16);
        acc = fmaf(s_mT[i*16 + k], v, acc);
    }
#pragma unroll
    for (int i=0;i<16;i++){
        float v = __shfl_sync(0xffffffffu, flcB, i, 16);
        acc = fmaf(s_mT[(16+i)*16 + k], v, acc);
    }
    g_feat1[p*16 + k] = fmaxf(fmaf(s_mg[k], acc, s_mb[k]), 0.0f);
}

// ================= Kernel C1: pool2 + p2m -> feat2 (32 ch) =================
__global__ __launch_bounds__(256,2) void kC1(const int* __restrict__ nidx,
    const float* __restrict__ fcW,
    const float* __restrict__ mW, const float* __restrict__ mg, const float* __restrict__ mb){
    __shared__ float s_fc[32*36];
    __shared__ float s_mT[32*32];     // transposed p2m: [in][out]
    __shared__ float s_mg[32], s_mb[32];
    int tid = threadIdx.x;
    for (int i = tid; i < 32*34; i += 256) s_fc[(i/34)*36 + (i%34)] = fcW[i];
    for (int i = tid; i < 1024; i += 256){ int o = i >> 5, c = i & 31; s_mT[c*32 + o] = mW[i]; }
    if (tid < 32){ s_mg[tid]=mg[tid]; s_mb[tid]=mb[tid]; }
    __syncthreads();

    int k = tid & 15, pg = tid >> 4;
    int p = blockIdx.x*16 + pg;
    int b = p / NN;
    int idx = nidx[p*KK + k];

    float in34[34];
    in34[0] = g_gdis[p*KK + k];
    const float4* fsrc = (const float4*)(g_feat1 + (b*NN + idx)*16);
    float4 q0 = fsrc[0], q1 = fsrc[1], q2 = fsrc[2], q3 = fsrc[3];
    in34[2]=q0.x;  in34[3]=q0.y;  in34[4]=q0.z;  in34[5]=q0.w;
    in34[6]=q1.x;  in34[7]=q1.y;  in34[8]=q1.z;  in34[9]=q1.w;
    in34[10]=q2.x; in34[11]=q2.y; in34[12]=q2.z; in34[13]=q2.w;
    in34[14]=q3.x; in34[15]=q3.y; in34[16]=q3.z; in34[17]=q3.w;
    const float4* csrc = (const float4*)(g_feat1 + p*16);
    float4 a0 = csrc[0], a1 = csrc[1], a2 = csrc[2], a3 = csrc[3];
    float sad = fabsf(a0.x-q0.x)+fabsf(a0.y-q0.y)+fabsf(a0.z-q0.z)+fabsf(a0.w-q0.w)
              + fabsf(a1.x-q1.x)+fabsf(a1.y-q1.y)+fabsf(a1.z-q1.z)+fabsf(a1.w-q1.w)
              + fabsf(a2.x-q2.x)+fabsf(a2.y-q2.y)+fabsf(a2.z-q2.z)+fabsf(a2.w-q2.w)
              + fabsf(a3.x-q3.x)+fabsf(a3.y-q3.y)+fabsf(a3.z-q3.z)+fabsf(a3.w-q3.w);
    in34[1] = 2.0f * fexp(-sad * 0.0625f);
    const float4* lsrc = (const float4*)(g_lrep2 + (p*KK + k)*16);
    float4 r0 = lsrc[0], r1 = lsrc[1], r2 = lsrc[2], r3 = lsrc[3];
    in34[18]=r0.x; in34[19]=r0.y; in34[20]=r0.z; in34[21]=r0.w;
    in34[22]=r1.x; in34[23]=r1.y; in34[24]=r1.z; in34[25]=r1.w;
    in34[26]=r2.x; in34[27]=r2.y; in34[28]=r2.z; in34[29]=r2.w;
    in34[30]=r3.x; in34[31]=r3.y; in34[32]=r3.z; in34[33]=r3.w;

    float flcA = 0.0f, flcB = 0.0f;
#pragma unroll
    for (int o=0;o<32;o++){
        float l = 0.0f;
#pragma unroll
        for (int c=0;c<34;c++) l = fmaf(s_fc[o*36+c], in34[c], l);
        float e  = fexp(l);
        float nu = e * in34[2+o];
        float es = rsum16(e);
        float ns = rsum16(nu);
        float flc = __fdividef(ns, es);
        if (o == k)      flcA = flc;
        if (o == k + 16) flcB = flc;
    }
    // p2m: lane k computes output channels k and k+16 (32 outs, 32 ins)
    float accA = 0.0f, accB = 0.0f;
#pragma unroll
    for (int i=0;i<16;i++){
        float v = __shfl_sync(0xffffffffu, flcA, i, 16);
        accA = fmaf(s_mT[i*32 + k],      v, accA);
        accB = fmaf(s_mT[i*32 + 16 + k], v, accB);
    }
#pragma unroll
    for (int i=0;i<16;i++){
        float v = __shfl_sync(0xffffffffu, flcB, i, 16);
        accA = fmaf(s_mT[(16+i)*32 + k],      v, accA);
        accB = fmaf(s_mT[(16+i)*32 + 16 + k], v, accB);
    }
    g_feat2[p*32 + k]      = fmaxf(fmaf(s_mg[k],    accA, s_mb[k]),    0.0f);
    g_feat2[p*32 + 16 + k] = fmaxf(fmaf(s_mg[16+k], accB, s_mb[16+k]), 0.0f);
}

// ============ Kernel C2: out = relu(m4 @ [m2@feat2 + sc@feature ; m3@[xyz,lg]]) ============
__global__ __launch_bounds__(256) void kC2(const float* __restrict__ feat,
                                           const float* __restrict__ xyz,
    const float* __restrict__ m2W, const float* __restrict__ m2g, const float* __restrict__ m2b,
    const float* __restrict__ scW, const float* __restrict__ scg, const float* __restrict__ scb,
    const float* __restrict__ m3W, const float* __restrict__ m3g, const float* __restrict__ m3b,
    const float* __restrict__ m4W, const float* __restrict__ m4g, const float* __restrict__ m4b,
    float* __restrict__ out){
    __shared__ float s_m2T[32*64];
    __shared__ float s_scT[16*64];
    __shared__ float s_m3T[4*64];
    __shared__ float s_m4T[128*64];
    __shared__ float s_m2g[64], s_m2b[64], s_scg[64], s_scb[64];
    __shared__ float s_m3g[64], s_m3b[64], s_m4g[64], s_m4b[64];
    int tid = threadIdx.x;
    for (int i = tid; i < 2048; i += 256){ int o = i >> 5,  c = i & 31;  s_m2T[c*64 + o] = m2W[i]; }
    for (int i = tid; i < 1024; i += 256){ int o = i >> 4,  c = i & 15;  s_scT[c*64 + o] = scW[i]; }
    for (int i = tid; i < 256;  i += 256){ int o = i >> 2,  c = i & 3;   s_m3T[c*64 + o] = m3W[i]; }
    for (int i = tid; i < 8192; i += 256){ int o = i >> 7,  c = i & 127; s_m4T[c*64 + o] = m4W[i]; }
    if (tid < 64){
        s_m2g[tid]=m2g[tid]; s_m2b[tid]=m2b[tid];
        s_scg[tid]=scg[tid]; s_scb[tid]=scb[tid];
        s_m3g[tid]=m3g[tid]; s_m3b[tid]=m3b[tid];
        s_m4g[tid]=m4g[tid]; s_m4b[tid]=m4b[tid];
    }
    __syncthreads();

    int j = tid & 15, pg = tid >> 4;
    int p = blockIdx.x*16 + pg;
    int b = p / NN, n = p - b*NN;

    float yA = g_feat2[p*32 + j];
    float yB = g_feat2[p*32 + 16 + j];
    float aLC[4] = {0,0,0,0};
#pragma unroll
    for (int i=0;i<16;i++){
        float v = __shfl_sync(0xffffffffu, yA, i, 16);
#pragma unroll
        for (int t=0;t<4;t++) aLC[t] = fmaf(s_m2T[i*64 + j + 16*t], v, aLC[t]);
    }
#pragma unroll
    for (int i=0;i<16;i++){
        float v = __shfl_sync(0xffffffffu, yB, i, 16);
#pragma unroll
        for (int t=0;t<4;t++) aLC[t] = fmaf(s_m2T[(16+i)*64 + j + 16*t], v, aLC[t]);
    }
    float xf = feat[(b*16 + j)*NN + n];
    float aSC[4] = {0,0,0,0};
#pragma unroll
    for (int i=0;i<16;i++){
        float v = __shfl_sync(0xffffffffu, xf, i, 16);
#pragma unroll
        for (int t=0;t<4;t++) aSC[t] = fmaf(s_scT[i*64 + j + 16*t], v, aSC[t]);
    }
    float cx = xyz[(b*NN + n)*3 + 0];
    float cy = xyz[(b*NN + n)*3 + 1];
    float cz = xyz[(b*NN + n)*3 + 2];
    float lg = g_lg[p];
    float z[4], gc[4];
#pragma unroll
    for (int t=0;t<4;t++){
        int o = j + 16*t;
        z[t] = fmaf(s_m2g[o], aLC[t], s_m2b[o]) + fmaf(s_scg[o], aSC[t], s_scb[o]);
        float a3 = s_m3T[0*64+o]*cx + s_m3T[1*64+o]*cy + s_m3T[2*64+o]*cz + s_m3T[3*64+o]*lg;
        gc[t] = fmaf(s_m3g[o], a3, s_m3b[o]);
    }
    float acc[4] = {0,0,0,0};
#pragma unroll
    for (int l=0;l<16;l++){
        float v0 = __shfl_sync(0xffffffffu, z[0],  l, 16);
        float v1 = __shfl_sync(0xffffffffu, z[1],  l, 16);
        float v2 = __shfl_sync(0xffffffffu, z[2],  l, 16);
        float v3 = __shfl_sync(0xffffffffu, z[3],  l, 16);
        float w0 = __shfl_sync(0xffffffffu, gc[0], l, 16);
        float w1 = __shfl_sync(0xffffffffu, gc[1], l, 16);
        float w2 = __shfl_sync(0xffffffffu, gc[2], l, 16);
        float w3 = __shfl_sync(0xffffffffu, gc[3], l, 16);
#pragma unroll
        for (int t=0;t<4;t++){
            int o = j + 16*t;
            acc[t] = fmaf(s_m4T[(l      )*64 + o], v0, acc[t]);
            acc[t] = fmaf(s_m4T[(16 + l )*64 + o], v1, acc[t]);
            acc[t] = fmaf(s_m4T[(32 + l )*64 + o], v2, acc[t]);
            acc[t] = fmaf(s_m4T[(48 + l )*64 + o], v3, acc[t]);
            acc[t] = fmaf(s_m4T[(64 + l )*64 + o], w0, acc[t]);
            acc[t] = fmaf(s_m4T[(80 + l )*64 + o], w1, acc[t]);
            acc[t] = fmaf(s_m4T[(96 + l )*64 + o], w2, acc[t]);
            acc[t] = fmaf(s_m4T[(112 + l)*64 + o], w3, acc[t]);
        }
    }
#pragma unroll
    for (int t=0;t<4;t++){
        int o = j + 16*t;
        out[(b*64 + o)*NN + n] = fmaxf(fmaf(s_m4g[o], acc[t], s_m4b[o]), 0.0f);
    }
}

extern "C" void kernel_launch(void* const* d_in, const int* in_sizes, int n_in,
                              void* d_out, int out_size){
    (void)in_sizes; (void)n_in; (void)out_size;
    const float* feature = (const float*)d_in[0];
    const float* xyz     = (const float*)d_in[1];
    const float* m1W  = (const float*)d_in[2];
    const float* m1g  = (const float*)d_in[3];
    const float* m1b  = (const float*)d_in[4];
    const float* lm1W = (const float*)d_in[5];
    const float* lm1g = (const float*)d_in[6];
    const float* lm1b = (const float*)d_in[7];
    const float* lm2W = (const float*)d_in[8];
    const float* lm2g = (const float*)d_in[9];
    const float* lm2b = (const float*)d_in[10];
    const float* p1fc = (const float*)d_in[11];
    const float* p1mW = (const float*)d_in[12];
    const float* p1mg = (const float*)d_in[13];
    const float* p1mb = (const float*)d_in[14];
    const float* p2fc = (const float*)d_in[15];
    const float* p2mW = (const float*)d_in[16];
    const float* p2mg = (const float*)d_in[17];
    const float* p2mb = (const float*)d_in[18];
    const float* m2W  = (const float*)d_in[19];
    const float* m2g  = (const float*)d_in[20];
    const float* m2b  = (const float*)d_in[21];
    const float* scW  = (const float*)d_in[22];
    const float* scg  = (const float*)d_in[23];
    const float* scb  = (const float*)d_in[24];
    const float* m3W  = (const float*)d_in[25];
    const float* m3g  = (const float*)d_in[26];
    const float* m3b  = (const float*)d_in[27];
    const float* m4W  = (const float*)d_in[28];
    const float* m4g  = (const float*)d_in[29];
    const float* m4b  = (const float*)d_in[30];
    const int*   nidx = (const int*)d_in[31];
    float* out = (float*)d_out;

    kA <<<NPTS/256, 256>>>(feature, m1W, m1g, m1b);
    kB <<<NPTS/16, 256>>>(xyz, nidx, lm1W, lm1g, lm1b, lm2W, lm2g, lm2b,
                          p1fc, p1mW, p1mg, p1mb);
    kC1<<<NPTS/16, 256>>>(nidx, p2fc, p2mW, p2mg, p2mb);
    kC2<<<NPTS/16, 256>>>(feature, xyz, m2W, m2g, m2b, scW, scg, scb,
                          m3W, m3g, m3b, m4W, m4g, m4b, out);
}

// round 4
// speedup vs baseline: 1.7101x; 1.7101x over previous
#include <cuda_runtime.h>
#include <math.h>

#define BB 4
#define NN 20480
#define KK 16
#define NPTS (BB*NN)

typedef unsigned long long u64;

// Scratch (static device globals — no allocation in kernel_launch)
__device__ __align__(16) float g_feat0[NPTS*16];
__device__ __align__(16) float g_feat1[NPTS*16];
__device__ __align__(16) float g_feat2[NPTS*32];
__device__ __align__(16) float g_lrep2[NPTS*KK*16];
__device__ __align__(16) float g_gdis[NPTS*KK];
__device__ __align__(16) float g_lg[NPTS];
__device__ __align__(16) u64   g_Ap[52*32];   // folded tail matrix, output-pair packed
__device__ __align__(16) float g_bias[64];

// ---------------- packed f32x2 helpers ----------------
__device__ __forceinline__ u64 pk2(float lo, float hi){
    u64 r; asm("mov.b64 %0,{%1,%2};" : "=l"(r) : "f"(lo), "f"(hi)); return r; }
__device__ __forceinline__ u64 dup2(float v){ return pk2(v,v); }
__device__ __forceinline__ void upk2(float& lo, float& hi, u64 v){
    asm("mov.b64 {%0,%1},%2;" : "=f"(lo), "=f"(hi) : "l"(v)); }
__device__ __forceinline__ u64 fma2(u64 a, u64 b, u64 c){
    u64 d; asm("fma.rn.f32x2 %0,%1,%2,%3;" : "=l"(d) : "l"(a),"l"(b),"l"(c)); return d; }
__device__ __forceinline__ u64 add2(u64 a, u64 b){
    u64 d; asm("add.rn.f32x2 %0,%1,%2;" : "=l"(d) : "l"(a),"l"(b)); return d; }
__device__ __forceinline__ u64 mul2(u64 a, u64 b){
    u64 d; asm("mul.rn.f32x2 %0,%1,%2;" : "=l"(d) : "l"(a),"l"(b)); return d; }

// ---------- fast math on the FMA pipe (avoid MUFU saturation) ----------
__device__ __forceinline__ float fexp(float x){
    x = fminf(fmaxf(x, -80.0f), 80.0f);
    const float L2E = 1.4426950408889634f;
    float z  = fmaf(x, L2E, 12582912.0f);
    float nf = z - 12582912.0f;
    float f  = fmaf(x, L2E, -nf);
    float p  = fmaf(f, 1.3333558147e-3f, 9.6181291076e-3f);
    p = fmaf(f, p, 5.5504108664e-2f);
    p = fmaf(f, p, 2.4022650696e-1f);
    p = fmaf(f, p, 6.9314718056e-1f);
    p = fmaf(f, p, 1.0f);
    int e = (__float_as_int(z) << 23) + 0x3F800000;
    return p * __int_as_float(e);
}

// two exps at once: scalar range-reduce, packed polynomial
__device__ __forceinline__ u64 fexp2s(float a, float b){
    a = fminf(fmaxf(a,-80.f),80.f)*1.4426950408889634f;
    b = fminf(fmaxf(b,-80.f),80.f)*1.4426950408889634f;
    float za = a + 12582912.f, zb = b + 12582912.f;
    float fa = a - (za - 12582912.f), fb = b - (zb - 12582912.f);
    u64 f2 = pk2(fa,fb);
    u64 p = fma2(f2, dup2(1.3333558147e-3f), dup2(9.6181291076e-3f));
    p = fma2(f2, p, dup2(5.5504108664e-2f));
    p = fma2(f2, p, dup2(2.4022650696e-1f));
    p = fma2(f2, p, dup2(6.9314718056e-1f));
    p = fma2(f2, p, dup2(1.0f));
    float sa = __int_as_float((__float_as_int(za)<<23)+0x3F800000);
    float sb = __int_as_float((__float_as_int(zb)<<23)+0x3F800000);
    return mul2(p, pk2(sa,sb));
}

__device__ __forceinline__ float fatan2(float y, float x){
    float ax = fabsf(x), ay = fabsf(y);
    float mx = fmaxf(ax, ay), mn = fminf(ax, ay);
    float a = (mx > 0.0f) ? __fdividef(mn, mx) : 0.0f;
    float s = a*a;
    float r = -0.0117212f;
    r = fmaf(r, s,  0.05265332f);
    r = fmaf(r, s, -0.11643287f);
    r = fmaf(r, s,  0.19354346f);
    r = fmaf(r, s, -0.33262347f);
    r = fmaf(r, s,  0.99997726f);
    r = r * a;
    if (ay > ax) r = 1.57079637f - r;
    if (x < 0.0f) r = 3.14159274f - r;
    if (y < 0.0f) r = -r;
    return r;
}

__device__ __forceinline__ float rsum16(float v){
    v += __shfl_xor_sync(0xffffffffu, v, 1);
    v += __shfl_xor_sync(0xffffffffu, v, 2);
    v += __shfl_xor_sync(0xffffffffu, v, 4);
    v += __shfl_xor_sync(0xffffffffu, v, 8);
    return v;
}
__device__ __forceinline__ float rmax16(float v){
    v = fmaxf(v, __shfl_xor_sync(0xffffffffu, v, 1));
    v = fmaxf(v, __shfl_xor_sync(0xffffffffu, v, 2));
    v = fmaxf(v, __shfl_xor_sync(0xffffffffu, v, 4));
    v = fmaxf(v, __shfl_xor_sync(0xffffffffu, v, 8));
    return v;
}

// =================== Kernel A: feat0 = relu(g*(m1_W@feature)+b) ===================
__global__ __launch_bounds__(256) void kA(const float* __restrict__ feat,
                                          const float* __restrict__ W,
                                          const float* __restrict__ gg,
                                          const float* __restrict__ bb){
    __shared__ float sW[256], sg[16], sb[16];
    int tid = threadIdx.x;
    sW[tid] = W[tid];
    if (tid < 16){ sg[tid]=gg[tid]; sb[tid]=bb[tid]; }
    __syncthreads();
    int p = blockIdx.x*256 + tid;
    int b = p / NN, n = p - b*NN;
    float x[16];
#pragma unroll
    for (int c=0;c<16;c++) x[c] = feat[(b*16 + c)*NN + n];
    float y[16];
#pragma unroll
    for (int o=0;o<16;o++){
        float acc = 0.0f;
#pragma unroll
        for (int c=0;c<16;c++) acc = fmaf(sW[o*16+c], x[c], acc);
        y[o] = fmaxf(fmaf(sg[o], acc, sb[o]), 0.0f);
    }
    float4* dst = (float4*)(g_feat0 + p*16);
    dst[0] = make_float4(y[0],y[1],y[2],y[3]);
    dst[1] = make_float4(y[4],y[5],y[6],y[7]);
    dst[2] = make_float4(y[8],y[9],y[10],y[11]);
    dst[3] = make_float4(y[12],y[13],y[14],y[15]);
}

// === kPre: fold m2/sc/m3/m4 (all linear) into one A[52][64] + bias[64] ===
__global__ void kPre(const float* __restrict__ m2W, const float* __restrict__ m2g, const float* __restrict__ m2b,
                     const float* __restrict__ scW, const float* __restrict__ scg, const float* __restrict__ scb,
                     const float* __restrict__ m3W, const float* __restrict__ m3g, const float* __restrict__ m3b,
                     const float* __restrict__ m4W, const float* __restrict__ m4g, const float* __restrict__ m4b){
    __shared__ float row[64];
    int c = blockIdx.x, o = threadIdx.x;
    float acc = 0.f;
    if (c < 32){
        for (int j=0;j<64;j++) acc = fmaf(m4W[o*128+j]*m2g[j], m2W[j*32+c], acc);
    } else if (c < 48){
        int cc = c-32;
        for (int j=0;j<64;j++) acc = fmaf(m4W[o*128+j]*scg[j], scW[j*16+cc], acc);
    } else {
        int cc = c-48;
        for (int j=0;j<64;j++) acc = fmaf(m4W[o*128+64+j]*m3g[j], m3W[j*4+cc], acc);
    }
    row[o] = m4g[o]*acc;
    __syncthreads();
    if (o < 32) g_Ap[c*32+o] = pk2(row[2*o], row[2*o+1]);
    if (c == 0){
        float s = 0.f;
        for (int j=0;j<64;j++)
            s += m4W[o*128+j]*(m2b[j]+scb[j]) + m4W[o*128+64+j]*m3b[j];
        g_bias[o] = fmaf(m4g[o], s, m4b[o]);
    }
}

// =========== Kernel B: geometry + lrep + lrep2 + pool1 + p1m -> feat1 ===========
__global__ __launch_bounds__(128) void kB(const float* __restrict__ xyz,
                                          const int*   __restrict__ nidx,
    const float* __restrict__ lm1W, const float* __restrict__ lm1g, const float* __restrict__ lm1b,
    const float* __restrict__ lm2W, const float* __restrict__ lm2g, const float* __restrict__ lm2b,
    const float* __restrict__ fcW,
    const float* __restrict__ mW, const float* __restrict__ mg, const float* __restrict__ mb){
    __shared__ ulonglong2 s_lm1p[5][8];
    __shared__ ulonglong2 s_lm2p[8][8];
    __shared__ ulonglong2 s_fcp[17][16];
    __shared__ u64 s_p1mp[16][16];
    __shared__ ulonglong2 s_red[8][16][17];   // [pg][opair][k] = {e2, nu2}
    __shared__ u64 s_flc[8][16];
    __shared__ float s_lm1g[16], s_lm1b[16], s_lm2g[16], s_lm2b[16], s_mg[16], s_mb[16];
    int tid = threadIdx.x;
    for (int i=tid; i<40; i+=128){ int cp=i/8, op=i%8; int c0=2*cp, c1=c0+1;
        ulonglong2 w;
        w.x = pk2(lm1W[(2*op)*9+c0], lm1W[(2*op+1)*9+c0]);
        w.y = (c1<9) ? pk2(lm1W[(2*op)*9+c1], lm1W[(2*op+1)*9+c1]) : 0ULL;
        s_lm1p[cp][op] = w; }
    for (int i=tid; i<64; i+=128){ int cp=i/8, op=i%8; int c0=2*cp, c1=c0+1;
        ulonglong2 w;
        w.x = pk2(lm2W[(2*op)*16+c0], lm2W[(2*op+1)*16+c0]);
        w.y = pk2(lm2W[(2*op)*16+c1], lm2W[(2*op+1)*16+c1]);
        s_lm2p[cp][op] = w; }
    for (int i=tid; i<272; i+=128){ int cp=i/16, op=i%16; int c0=2*cp, c1=c0+1;
        ulonglong2 w;
        w.x = pk2(fcW[(2*op)*34+c0], fcW[(2*op+1)*34+c0]);
        w.y = pk2(fcW[(2*op)*34+c1], fcW[(2*op+1)*34+c1]);
        s_fcp[cp][op] = w; }
    for (int i=tid; i<256; i+=128){ int cp=i/16, o=i%16;
        s_p1mp[cp][o] = pk2(mW[o*32+2*cp], mW[o*32+2*cp+1]); }
    if (tid < 16){
        s_lm1g[tid]=lm1g[tid]; s_lm1b[tid]=lm1b[tid];
        s_lm2g[tid]=lm2g[tid]; s_lm2b[tid]=lm2b[tid];
        s_mg[tid]=mg[tid];     s_mb[tid]=mb[tid];
    }
    __syncthreads();

    int k = tid & 15, pg = tid >> 4;
    int p = blockIdx.x*8 + pg;
    int b = p / NN, n = p - b*NN;
    const float* xb = xyz + b*(NN*3);
    int idx = nidx[p*KK + k];
    float nx = xb[idx*3+0], ny = xb[idx*3+1], nz = xb[idx*3+2];
    float cx = xb[n*3+0],   cy = xb[n*3+1],   cz = xb[n*3+2];
    float rx = cx-nx, ry = cy-ny, rz = cz-nz;
    float dxy2 = fmaf(rx,rx, ry*ry);
    float rdis = sqrtf(dxy2 + rz*rz);
    float gdis = fexp(-rdis);
    float ralpha = fatan2(ry, rx);
    float rbeta  = fatan2(rz, sqrtf(dxy2));
    float mxn = rsum16(nx)*0.0625f;
    float myn = rsum16(ny)*0.0625f;
    float mzn = rsum16(nz)*0.0625f;
    float dx = cx - mxn, dy = cy - myn, dz = cz - mzn;
    float dalpha = fatan2(dy, dx);
    float dbeta  = fatan2(dz, sqrtf(fmaf(dx,dx,dy*dy)));
    float mr = rmax16(rdis);
    if (k == 0){
        float cn = sqrtf(cx*cx + cy*cy + cz*cz);
        g_lg[p] = __fdividef(mr*mr*mr, cn*cn*cn);
    }
    g_gdis[p*KK + k] = gdis;

    float lr[10] = { ralpha - dalpha, rbeta - dbeta, rdis, cx, cy, cz, nx, ny, nz, 0.0f };

    float in34[34];
    in34[0] = gdis;
    // lrep = relu(lm1) — packed output pairs
    {
        u64 l1[8] = {0ULL,0ULL,0ULL,0ULL,0ULL,0ULL,0ULL,0ULL};
#pragma unroll
        for (int cp=0;cp<5;cp++){
            u64 a0 = dup2(lr[2*cp]), a1 = dup2(lr[2*cp+1]);
#pragma unroll
            for (int op=0;op<8;op++){
                ulonglong2 w = s_lm1p[cp][op];
                l1[op] = fma2(w.x, a0, l1[op]);
                l1[op] = fma2(w.y, a1, l1[op]);
            }
        }
#pragma unroll
        for (int op=0;op<8;op++){
            float lo,hi; upk2(lo,hi,l1[op]);
            in34[18+2*op]   = fmaxf(fmaf(s_lm1g[2*op],   lo, s_lm1b[2*op]),   0.f);
            in34[18+2*op+1] = fmaxf(fmaf(s_lm1g[2*op+1], hi, s_lm1b[2*op+1]), 0.f);
        }
    }
    // lrep2 = relu(lm2 @ lrep), store for pool2
    {
        u64 l2[8] = {0ULL,0ULL,0ULL,0ULL,0ULL,0ULL,0ULL,0ULL};
#pragma unroll
        for (int cp=0;cp<8;cp++){
            u64 a0 = dup2(in34[18+2*cp]), a1 = dup2(in34[19+2*cp]);
#pragma unroll
            for (int op=0;op<8;op++){
                ulonglong2 w = s_lm2p[cp][op];
                l2[op] = fma2(w.x, a0, l2[op]);
                l2[op] = fma2(w.y, a1, l2[op]);
            }
        }
        float l2v[16];
#pragma unroll
        for (int op=0;op<8;op++){
            float lo,hi; upk2(lo,hi,l2[op]);
            l2v[2*op]   = fmaxf(fmaf(s_lm2g[2*op],   lo, s_lm2b[2*op]),   0.f);
            l2v[2*op+1] = fmaxf(fmaf(s_lm2g[2*op+1], hi, s_lm2b[2*op+1]), 0.f);
        }
        float4* ldst = (float4*)(g_lrep2 + (p*KK + k)*16);
        ldst[0] = make_float4(l2v[0],l2v[1],l2v[2],l2v[3]);
        ldst[1] = make_float4(l2v[4],l2v[5],l2v[6],l2v[7]);
        ldst[2] = make_float4(l2v[8],l2v[9],l2v[10],l2v[11]);
        ldst[3] = make_float4(l2v[12],l2v[13],l2v[14],l2v[15]);
    }

    // gather neighbor features + feature distance
    const float4* fsrc = (const float4*)(g_feat0 + (b*NN + idx)*16);
    float4 q0 = fsrc[0], q1 = fsrc[1], q2 = fsrc[2], q3 = fsrc[3];
    in34[2]=q0.x;  in34[3]=q0.y;  in34[4]=q0.z;  in34[5]=q0.w;
    in34[6]=q1.x;  in34[7]=q1.y;  in34[8]=q1.z;  in34[9]=q1.w;
    in34[10]=q2.x; in34[11]=q2.y; in34[12]=q2.z; in34[13]=q2.w;
    in34[14]=q3.x; in34[15]=q3.y; in34[16]=q3.z; in34[17]=q3.w;
    const float4* csrc = (const float4*)(g_feat0 + p*16);
    float4 a0 = csrc[0], a1 = csrc[1], a2 = csrc[2], a3 = csrc[3];
    float sad = fabsf(a0.x-q0.x)+fabsf(a0.y-q0.y)+fabsf(a0.z-q0.z)+fabsf(a0.w-q0.w)
              + fabsf(a1.x-q1.x)+fabsf(a1.y-q1.y)+fabsf(a1.z-q1.z)+fabsf(a1.w-q1.w)
              + fabsf(a2.x-q2.x)+fabsf(a2.y-q2.y)+fabsf(a2.z-q2.z)+fabsf(a2.w-q2.w)
              + fabsf(a3.x-q3.x)+fabsf(a3.y-q3.y)+fabsf(a3.z-q3.z)+fabsf(a3.w-q3.w);
    in34[1] = 2.0f * fexp(-sad * 0.0625f);

    // attentive pool FC (packed output pairs)
    u64 fc[16];
#pragma unroll
    for (int op=0;op<16;op++) fc[op]=0ULL;
#pragma unroll
    for (int cp=0;cp<17;cp++){
        u64 a0d = dup2(in34[2*cp]), a1d = dup2(in34[2*cp+1]);
#pragma unroll
        for (int op=0;op<16;op++){
            ulonglong2 w = s_fcp[cp][op];
            fc[op] = fma2(w.x, a0d, fc[op]);
            fc[op] = fma2(w.y, a1d, fc[op]);
        }
    }
    // exp + numerator, deposit to transpose tile
#pragma unroll
    for (int op=0;op<16;op++){
        float lo,hi; upk2(lo,hi,fc[op]);
        u64 e2 = fexp2s(lo,hi);
        u64 f2 = pk2(in34[2+2*op], in34[3+2*op]);
        ulonglong2 st; st.x = e2; st.y = mul2(e2, f2);
        s_red[pg][op][k] = st;
    }
    __syncwarp();
    // lane k reduces channel pair op=k over all 16 neighbors
    u64 es = 0ULL, ns = 0ULL;
#pragma unroll
    for (int k2=0;k2<16;k2++){
        ulonglong2 v = s_red[pg][k][k2];
        es = add2(es, v.x); ns = add2(ns, v.y);
    }
    {
        float el,eh,nl,nh; upk2(el,eh,es); upk2(nl,nh,ns);
        s_flc[pg][k] = pk2(__fdividef(nl,el), __fdividef(nh,eh));
    }
    __syncwarp();
    // p1m: lane k computes output channel k (packed over input pairs)
    u64 acc = 0ULL;
#pragma unroll
    for (int cp=0;cp<16;cp++) acc = fma2(s_p1mp[cp][k], s_flc[pg][cp], acc);
    float al,ah; upk2(al,ah,acc);
    g_feat1[p*16 + k] = fmaxf(fmaf(s_mg[k], al+ah, s_mb[k]), 0.0f);
}

// ================= Kernel C1: pool2 + p2m -> feat2 (32 ch) =================
__global__ __launch_bounds__(128) void kC1(const int* __restrict__ nidx,
    const float* __restrict__ fcW,
    const float* __restrict__ mW, const float* __restrict__ mg, const float* __restrict__ mb){
    __shared__ ulonglong2 s_fcp[17][16];
    __shared__ u64 s_p2mp[16][32];
    __shared__ ulonglong2 s_red[8][16][17];
    __shared__ u64 s_flc[8][16];
    __shared__ float s_mg[32], s_mb[32];
    int tid = threadIdx.x;
    for (int i=tid; i<272; i+=128){ int cp=i/16, op=i%16; int c0=2*cp, c1=c0+1;
        ulonglong2 w;
        w.x = pk2(fcW[(2*op)*34+c0], fcW[(2*op+1)*34+c0]);
        w.y = pk2(fcW[(2*op)*34+c1], fcW[(2*op+1)*34+c1]);
        s_fcp[cp][op] = w; }
    for (int i=tid; i<512; i+=128){ int cp=i>>5, o=i&31;
        s_p2mp[cp][o] = pk2(mW[o*32+2*cp], mW[o*32+2*cp+1]); }
    if (tid < 32){ s_mg[tid]=mg[tid]; s_mb[tid]=mb[tid]; }
    __syncthreads();

    int k = tid & 15, pg = tid >> 4;
    int p = blockIdx.x*8 + pg;
    int b = p / NN;
    int idx = nidx[p*KK + k];

    float in34[34];
    in34[0] = g_gdis[p*KK + k];
    const float4* fsrc = (const float4*)(g_feat1 + (b*NN + idx)*16);
    float4 q0 = fsrc[0], q1 = fsrc[1], q2 = fsrc[2], q3 = fsrc[3];
    in34[2]=q0.x;  in34[3]=q0.y;  in34[4]=q0.z;  in34[5]=q0.w;
    in34[6]=q1.x;  in34[7]=q1.y;  in34[8]=q1.z;  in34[9]=q1.w;
    in34[10]=q2.x; in34[11]=q2.y; in34[12]=q2.z; in34[13]=q2.w;
    in34[14]=q3.x; in34[15]=q3.y; in34[16]=q3.z; in34[17]=q3.w;
    const float4* csrc = (const float4*)(g_feat1 + p*16);
    float4 a0 = csrc[0], a1 = csrc[1], a2 = csrc[2], a3 = csrc[3];
    float sad = fabsf(a0.x-q0.x)+fabsf(a0.y-q0.y)+fabsf(a0.z-q0.z)+fabsf(a0.w-q0.w)
              + fabsf(a1.x-q1.x)+fabsf(a1.y-q1.y)+fabsf(a1.z-q1.z)+fabsf(a1.w-q1.w)
              + fabsf(a2.x-q2.x)+fabsf(a2.y-q2.y)+fabsf(a2.z-q2.z)+fabsf(a2.w-q2.w)
              + fabsf(a3.x-q3.x)+fabsf(a3.y-q3.y)+fabsf(a3.z-q3.z)+fabsf(a3.w-q3.w);
    in34[1] = 2.0f * fexp(-sad * 0.0625f);
    const float4* lsrc = (const float4*)(g_lrep2 + (p*KK + k)*16);
    float4 r0 = lsrc[0], r1 = lsrc[1], r2 = lsrc[2], r3 = lsrc[3];
    in34[18]=r0.x; in34[19]=r0.y; in34[20]=r0.z; in34[21]=r0.w;
    in34[22]=r1.x; in34[23]=r1.y; in34[24]=r1.z; in34[25]=r1.w;
    in34[26]=r2.x; in34[27]=r2.y; in34[28]=r2.z; in34[29]=r2.w;
    in34[30]=r3.x; in34[31]=r3.y; in34[32]=r3.z; in34[33]=r3.w;

    u64 fc[16];
#pragma unroll
    for (int op=0;op<16;op++) fc[op]=0ULL;
#pragma unroll
    for (int cp=0;cp<17;cp++){
        u64 a0d = dup2(in34[2*cp]), a1d = dup2(in34[2*cp+1]);
#pragma unroll
        for (int op=0;op<16;op++){
            ulonglong2 w = s_fcp[cp][op];
            fc[op] = fma2(w.x, a0d, fc[op]);
            fc[op] = fma2(w.y, a1d, fc[op]);
        }
    }
#pragma unroll
    for (int op=0;op<16;op++){
        float lo,hi; upk2(lo,hi,fc[op]);
        u64 e2 = fexp2s(lo,hi);
        u64 f2 = pk2(in34[2+2*op], in34[3+2*op]);
        ulonglong2 st; st.x = e2; st.y = mul2(e2, f2);
        s_red[pg][op][k] = st;
    }
    __syncwarp();
    u64 es = 0ULL, ns = 0ULL;
#pragma unroll
    for (int k2=0;k2<16;k2++){
        ulonglong2 v = s_red[pg][k][k2];
        es = add2(es, v.x); ns = add2(ns, v.y);
    }
    {
        float el,eh,nl,nh; upk2(el,eh,es); upk2(nl,nh,ns);
        s_flc[pg][k] = pk2(__fdividef(nl,el), __fdividef(nh,eh));
    }
    __syncwarp();
    // p2m: lane k computes output channels 2k and 2k+1 (packed over input pairs)
    u64 accA = 0ULL, accB = 0ULL;
#pragma unroll
    for (int cp=0;cp<16;cp++){
        ulonglong2 w = *reinterpret_cast<const ulonglong2*>(&s_p2mp[cp][2*k]);
        u64 f = s_flc[pg][cp];
        accA = fma2(w.x, f, accA);
        accB = fma2(w.y, f, accB);
    }
    float xl,xh,yl,yh; upk2(xl,xh,accA); upk2(yl,yh,accB);
    g_feat2[p*32 + 2*k]   = fmaxf(fmaf(s_mg[2*k],   xl+xh, s_mb[2*k]),   0.0f);
    g_feat2[p*32 + 2*k+1] = fmaxf(fmaf(s_mg[2*k+1], yl+yh, s_mb[2*k+1]), 0.0f);
}

// ============ Kernel C2: out = relu(A @ [feat2;feature;xyz;lg] + bias) ============
__global__ __launch_bounds__(256) void kC2(const float* __restrict__ feat,
                                           const float* __restrict__ xyz,
                                           float* __restrict__ out){
    __shared__ u64   s_Ap[52][32];
    __shared__ float s_X[52][68];
    __shared__ float s_bias[64];
    int tid = threadIdx.x;
    int p0 = blockIdx.x*64;
    int b = p0 / NN, n0 = p0 - b*NN;
    for (int i=tid; i<52*32; i+=256) s_Ap[i>>5][i&31] = g_Ap[i];
    if (tid < 64) s_bias[tid] = g_bias[tid];
    for (int i=tid; i<512; i+=256){
        float4 v = ((const float4*)g_feat2)[p0*8 + i];
        int pt = i>>3, c = (i&7)*4;
        s_X[c][pt]=v.x; s_X[c+1][pt]=v.y; s_X[c+2][pt]=v.z; s_X[c+3][pt]=v.w;
    }
    for (int i=tid; i<1024; i+=256){
        int row = i>>6, pt = i&63;
        s_X[32+row][pt] = feat[(b*16+row)*NN + n0 + pt];
    }
    for (int i=tid; i<192; i+=256){
        int pt = i/3, d = i - pt*3;
        s_X[48+d][pt] = xyz[(b*NN + n0 + pt)*3 + d];
    }
    for (int i=tid; i<64; i+=256) s_X[51][i] = g_lg[p0+i];
    __syncthreads();

    int i4 = tid >> 4;   // output quad: o0 = 4*i4
    int j  = tid & 15;   // point quad:  pt = 4*j..4*j+3
    u64 acc[8];
#pragma unroll
    for (int t=0;t<8;t++) acc[t]=0ULL;
#pragma unroll
    for (int c=0;c<52;c++){
        ulonglong2 w = *reinterpret_cast<const ulonglong2*>(&s_Ap[c][2*i4]);
        float4 x = *reinterpret_cast<const float4*>(&s_X[c][4*j]);
        u64 d0=dup2(x.x), d1=dup2(x.y), d2=dup2(x.z), d3=dup2(x.w);
        acc[0]=fma2(w.x,d0,acc[0]); acc[1]=fma2(w.y,d0,acc[1]);
        acc[2]=fma2(w.x,d1,acc[2]); acc[3]=fma2(w.y,d1,acc[3]);
        acc[4]=fma2(w.x,d2,acc[4]); acc[5]=fma2(w.y,d2,acc[5]);
        acc[6]=fma2(w.x,d3,acc[6]); acc[7]=fma2(w.y,d3,acc[7]);
    }
    float r[4][4];
#pragma unroll
    for (int q=0;q<4;q++){
        upk2(r[q][0], r[q][1], acc[q*2]);
        upk2(r[q][2], r[q][3], acc[q*2+1]);
    }
#pragma unroll
    for (int oo=0;oo<4;oo++){
        int o = 4*i4 + oo;
        float bb = s_bias[o];
        float4 st = make_float4(
            fmaxf(r[0][oo]+bb, 0.f), fmaxf(r[1][oo]+bb, 0.f),
            fmaxf(r[2][oo]+bb, 0.f), fmaxf(r[3][oo]+bb, 0.f));
        *reinterpret_cast<float4*>(&out[(b*64+o)*NN + n0 + 4*j]) = st;
    }
}

extern "C" void kernel_launch(void* const* d_in, const int* in_sizes, int n_in,
                              void* d_out, int out_size){
    (void)in_sizes; (void)n_in; (void)out_size;
    const float* feature = (const float*)d_in[0];
    const float* xyz     = (const float*)d_in[1];
    const float* m1W  = (const float*)d_in[2];
    const float* m1g  = (const float*)d_in[3];
    const float* m1b  = (const float*)d_in[4];
    const float* lm1W = (const float*)d_in[5];
    const float* lm1g = (const float*)d_in[6];
    const float* lm1b = (const float*)d_in[7];
    const float* lm2W = (const float*)d_in[8];
    const float* lm2g = (const float*)d_in[9];
    const float* lm2b = (const float*)d_in[10];
    const float* p1fc = (const float*)d_in[11];
    const float* p1mW = (const float*)d_in[12];
    const float* p1mg = (const float*)d_in[13];
    const float* p1mb = (const float*)d_in[14];
    const float* p2fc = (const float*)d_in[15];
    const float* p2mW = (const float*)d_in[16];
    const float* p2mg = (const float*)d_in[17];
    const float* p2mb = (const float*)d_in[18];
    const float* m2W  = (const float*)d_in[19];
    const float* m2g  = (const float*)d_in[20];
    const float* m2b  = (const float*)d_in[21];
    const float* scW  = (const float*)d_in[22];
    const float* scg  = (const float*)d_in[23];
    const float* scb  = (const float*)d_in[24];
    const float* m3W  = (const float*)d_in[25];
    const float* m3g  = (const float*)d_in[26];
    const float* m3b  = (const float*)d_in[27];
    const float* m4W  = (const float*)d_in[28];
    const float* m4g  = (const float*)d_in[29];
    const float* m4b  = (const float*)d_in[30];
    const int*   nidx = (const int*)d_in[31];
    float* out = (float*)d_out;

    kPre<<<52, 64>>>(m2W,m2g,m2b, scW,scg,scb, m3W,m3g,m3b, m4W,m4g,m4b);
    kA  <<<NPTS/256, 256>>>(feature, m1W, m1g, m1b);
    kB  <<<NPTS/8, 128>>>(xyz, nidx, lm1W, lm1g, lm1b, lm2W, lm2g, lm2b,
                          p1fc, p1mW, p1mg, p1mb);
    kC1 <<<NPTS/8, 128>>>(nidx, p2fc, p2mW, p2mg, p2mb);
    kC2 <<<NPTS/64, 256>>>(feature, xyz, out);
}

// round 5
// speedup vs baseline: 2.1098x; 1.2337x over previous
#include <cuda_runtime.h>
#include <math.h>

#define BB 4
#define NN 20480
#define KK 16
#define NPTS (BB*NN)

typedef unsigned long long u64;

// Scratch (static device globals — no allocation in kernel_launch)
__device__ __align__(16) float g_feat0[NPTS*16];
__device__ __align__(16) float g_feat1[NPTS*16];
__device__ __align__(16) float g_feat2[NPTS*32];
__device__ __align__(16) float g_lrep2[NPTS*KK*16];
__device__ __align__(16) float g_gdis[NPTS*KK];
__device__ __align__(16) float g_lg[NPTS];
__device__ __align__(16) u64   g_Ap[52*32];
__device__ __align__(16) float g_bias[64];

// Warp-uniform, literal-indexed weights -> constant bank (LDCU path, off the L1 crossbar)
__constant__ float c_m1[256];
__constant__ float c_m1g[16];
__constant__ float c_m1b[16];
__constant__ float c_lm1[144];
__constant__ float c_lm1g[16];
__constant__ float c_lm1b[16];
__constant__ float c_lm2[256];
__constant__ float c_lm2g[16];
__constant__ float c_lm2b[16];
__constant__ float c_fc1[1088];
__constant__ float c_fc2[1088];

// ---------------- packed f32x2 helpers ----------------
__device__ __forceinline__ u64 pk2(float lo, float hi){
    u64 r; asm("mov.b64 %0,{%1,%2};" : "=l"(r) : "f"(lo), "f"(hi)); return r; }
__device__ __forceinline__ u64 dup2(float v){ return pk2(v,v); }
__device__ __forceinline__ void upk2(float& lo, float& hi, u64 v){
    asm("mov.b64 {%0,%1},%2;" : "=f"(lo), "=f"(hi) : "l"(v)); }
__device__ __forceinline__ u64 fma2(u64 a, u64 b, u64 c){
    u64 d; asm("fma.rn.f32x2 %0,%1,%2,%3;" : "=l"(d) : "l"(a),"l"(b),"l"(c)); return d; }
__device__ __forceinline__ u64 add2(u64 a, u64 b){
    u64 d; asm("add.rn.f32x2 %0,%1,%2;" : "=l"(d) : "l"(a),"l"(b)); return d; }
__device__ __forceinline__ u64 mul2(u64 a, u64 b){
    u64 d; asm("mul.rn.f32x2 %0,%1,%2;" : "=l"(d) : "l"(a),"l"(b)); return d; }

// ---------- fast math on the FMA pipe (avoid MUFU saturation) ----------
__device__ __forceinline__ float fexp(float x){
    x = fminf(fmaxf(x, -80.0f), 80.0f);
    const float L2E = 1.4426950408889634f;
    float z  = fmaf(x, L2E, 12582912.0f);
    float nf = z - 12582912.0f;
    float f  = fmaf(x, L2E, -nf);
    float p  = fmaf(f, 1.3333558147e-3f, 9.6181291076e-3f);
    p = fmaf(f, p, 5.5504108664e-2f);
    p = fmaf(f, p, 2.4022650696e-1f);
    p = fmaf(f, p, 6.9314718056e-1f);
    p = fmaf(f, p, 1.0f);
    int e = (__float_as_int(z) << 23) + 0x3F800000;
    return p * __int_as_float(e);
}

// two exps at once: scalar range-reduce, packed polynomial
__device__ __forceinline__ u64 fexp2s(float a, float b){
    a = fminf(fmaxf(a,-80.f),80.f)*1.4426950408889634f;
    b = fminf(fmaxf(b,-80.f),80.f)*1.4426950408889634f;
    float za = a + 12582912.f, zb = b + 12582912.f;
    float fa = a - (za - 12582912.f), fb = b - (zb - 12582912.f);
    u64 f2 = pk2(fa,fb);
    u64 p = fma2(f2, dup2(1.3333558147e-3f), dup2(9.6181291076e-3f));
    p = fma2(f2, p, dup2(5.5504108664e-2f));
    p = fma2(f2, p, dup2(2.4022650696e-1f));
    p = fma2(f2, p, dup2(6.9314718056e-1f));
    p = fma2(f2, p, dup2(1.0f));
    float sa = __int_as_float((__float_as_int(za)<<23)+0x3F800000);
    float sb = __int_as_float((__float_as_int(zb)<<23)+0x3F800000);
    return mul2(p, pk2(sa,sb));
}

__device__ __forceinline__ float fatan2(float y, float x){
    float ax = fabsf(x), ay = fabsf(y);
    float mx = fmaxf(ax, ay), mn = fminf(ax, ay);
    float a = (mx > 0.0f) ? __fdividef(mn, mx) : 0.0f;
    float s = a*a;
    float r = -0.0117212f;
    r = fmaf(r, s,  0.05265332f);
    r = fmaf(r, s, -0.11643287f);
    r = fmaf(r, s,  0.19354346f);
    r = fmaf(r, s, -0.33262347f);
    r = fmaf(r, s,  0.99997726f);
    r = r * a;
    if (ay > ax) r = 1.57079637f - r;
    if (x < 0.0f) r = 3.14159274f - r;
    if (y < 0.0f) r = -r;
    return r;
}

__device__ __forceinline__ float rsum16(float v){
    v += __shfl_xor_sync(0xffffffffu, v, 1);
    v += __shfl_xor_sync(0xffffffffu, v, 2);
    v += __shfl_xor_sync(0xffffffffu, v, 4);
    v += __shfl_xor_sync(0xffffffffu, v, 8);
    return v;
}
__device__ __forceinline__ float rmax16(float v){
    v = fmaxf(v, __shfl_xor_sync(0xffffffffu, v, 1));
    v = fmaxf(v, __shfl_xor_sync(0xffffffffu, v, 2));
    v = fmaxf(v, __shfl_xor_sync(0xffffffffu, v, 4));
    v = fmaxf(v, __shfl_xor_sync(0xffffffffu, v, 8));
    return v;
}

// =================== Kernel A: feat0 = relu(g*(m1_W@feature)+b) ===================
__global__ __launch_bounds__(256) void kA(const float* __restrict__ feat){
    int tid = threadIdx.x;
    int p = blockIdx.x*256 + tid;
    int b = p / NN, n = p - b*NN;
    float x[16];
#pragma unroll
    for (int c=0;c<16;c++) x[c] = feat[(b*16 + c)*NN + n];
    float y[16];
#pragma unroll
    for (int o=0;o<16;o++) y[o] = 0.0f;
#pragma unroll
    for (int c=0;c<16;c++){
        float xv = x[c];
#pragma unroll
        for (int o=0;o<16;o++) y[o] = fmaf(c_m1[o*16+c], xv, y[o]);
    }
#pragma unroll
    for (int o=0;o<16;o++) y[o] = fmaxf(fmaf(c_m1g[o], y[o], c_m1b[o]), 0.0f);
    float4* dst = (float4*)(g_feat0 + p*16);
    dst[0] = make_float4(y[0],y[1],y[2],y[3]);
    dst[1] = make_float4(y[4],y[5],y[6],y[7]);
    dst[2] = make_float4(y[8],y[9],y[10],y[11]);
    dst[3] = make_float4(y[12],y[13],y[14],y[15]);
}

// === kPre: fold m2/sc/m3/m4 (all linear) into one A[52][64] + bias[64] ===
__global__ void kPre(const float* __restrict__ m2W, const float* __restrict__ m2g, const float* __restrict__ m2b,
                     const float* __restrict__ scW, const float* __restrict__ scg, const float* __restrict__ scb,
                     const float* __restrict__ m3W, const float* __restrict__ m3g, const float* __restrict__ m3b,
                     const float* __restrict__ m4W, const float* __restrict__ m4g, const float* __restrict__ m4b){
    __shared__ float row[64];
    int c = blockIdx.x, o = threadIdx.x;
    float acc = 0.f;
    if (c < 32){
        for (int j=0;j<64;j++) acc = fmaf(m4W[o*128+j]*m2g[j], m2W[j*32+c], acc);
    } else if (c < 48){
        int cc = c-32;
        for (int j=0;j<64;j++) acc = fmaf(m4W[o*128+j]*scg[j], scW[j*16+cc], acc);
    } else {
        int cc = c-48;
        for (int j=0;j<64;j++) acc = fmaf(m4W[o*128+64+j]*m3g[j], m3W[j*4+cc], acc);
    }
    row[o] = m4g[o]*acc;
    __syncthreads();
    if (o < 32) g_Ap[c*32+o] = pk2(row[2*o], row[2*o+1]);
    if (c == 0){
        float s = 0.f;
        for (int j=0;j<64;j++)
            s += m4W[o*128+j]*(m2b[j]+scb[j]) + m4W[o*128+64+j]*m3b[j];
        g_bias[o] = fmaf(m4g[o], s, m4b[o]);
    }
}

// =========== Kernel B: geometry + lrep + lrep2 + pool1 + p1m -> feat1 ===========
__global__ __launch_bounds__(128) void kB(const float* __restrict__ xyz,
                                          const int*   __restrict__ nidx,
                                          const float* __restrict__ mW,
                                          const float* __restrict__ mg,
                                          const float* __restrict__ mb){
    __shared__ u64 s_p1mp[16][16];          // lane-indexed: stays in smem
    __shared__ ulonglong2 s_red[8][16][9];  // [pg][k][opair] = {e2, nu2}, pad 9 (k-major)
    __shared__ u64 s_flc[8][16];
    __shared__ float s_mg[16], s_mb[16];
    int tid = threadIdx.x;
    for (int i=tid; i<256; i+=128){ int cp=i>>4, o=i&15;
        s_p1mp[cp][o] = pk2(mW[o*32+2*cp], mW[o*32+2*cp+1]); }
    if (tid < 16){ s_mg[tid]=mg[tid]; s_mb[tid]=mb[tid]; }
    __syncthreads();

    int k = tid & 15, pg = tid >> 4;
    int p = blockIdx.x*8 + pg;
    int b = p / NN, n = p - b*NN;
    const float* xb = xyz + b*(NN*3);
    int idx = nidx[p*KK + k];
    float nx = xb[idx*3+0], ny = xb[idx*3+1], nz = xb[idx*3+2];
    float cx = xb[n*3+0],   cy = xb[n*3+1],   cz = xb[n*3+2];
    float rx = cx-nx, ry = cy-ny, rz = cz-nz;
    float dxy2 = fmaf(rx,rx, ry*ry);
    float rdis = sqrtf(dxy2 + rz*rz);
    float gdis = fexp(-rdis);
    float ralpha = fatan2(ry, rx);
    float rbeta  = fatan2(rz, sqrtf(dxy2));
    float mxn = rsum16(nx)*0.0625f;
    float myn = rsum16(ny)*0.0625f;
    float mzn = rsum16(nz)*0.0625f;
    float dx = cx - mxn, dy = cy - myn, dz = cz - mzn;
    float dalpha = fatan2(dy, dx);
    float dbeta  = fatan2(dz, sqrtf(fmaf(dx,dx,dy*dy)));
    float mr = rmax16(rdis);
    if (k == 0){
        float cn = sqrtf(cx*cx + cy*cy + cz*cz);
        g_lg[p] = __fdividef(mr*mr*mr, cn*cn*cn);
    }
    g_gdis[p*KK + k] = gdis;

    float lr[9] = { ralpha - dalpha, rbeta - dbeta, rdis, cx, cy, cz, nx, ny, nz };

    float in34[34];
    in34[0] = gdis;
    // lrep = relu(lm1) — scalar FFMA from constant bank
    {
        float l1v[16];
#pragma unroll
        for (int o=0;o<16;o++) l1v[o]=0.f;
#pragma unroll
        for (int c=0;c<9;c++){
            float xv = lr[c];
#pragma unroll
            for (int o=0;o<16;o++) l1v[o] = fmaf(c_lm1[o*9+c], xv, l1v[o]);
        }
#pragma unroll
        for (int o=0;o<16;o++)
            in34[18+o] = fmaxf(fmaf(c_lm1g[o], l1v[o], c_lm1b[o]), 0.f);
    }
    // lrep2 = relu(lm2 @ lrep), store for pool2
    {
        float l2v[16];
#pragma unroll
        for (int o=0;o<16;o++) l2v[o]=0.f;
#pragma unroll
        for (int c=0;c<16;c++){
            float xv = in34[18+c];
#pragma unroll
            for (int o=0;o<16;o++) l2v[o] = fmaf(c_lm2[o*16+c], xv, l2v[o]);
        }
#pragma unroll
        for (int o=0;o<16;o++)
            l2v[o] = fmaxf(fmaf(c_lm2g[o], l2v[o], c_lm2b[o]), 0.f);
        float4* ldst = (float4*)(g_lrep2 + (p*KK + k)*16);
        ldst[0] = make_float4(l2v[0],l2v[1],l2v[2],l2v[3]);
        ldst[1] = make_float4(l2v[4],l2v[5],l2v[6],l2v[7]);
        ldst[2] = make_float4(l2v[8],l2v[9],l2v[10],l2v[11]);
        ldst[3] = make_float4(l2v[12],l2v[13],l2v[14],l2v[15]);
    }

    // gather neighbor features + feature distance
    const float4* fsrc = (const float4*)(g_feat0 + (b*NN + idx)*16);
    float4 q0 = fsrc[0], q1 = fsrc[1], q2 = fsrc[2], q3 = fsrc[3];
    in34[2]=q0.x;  in34[3]=q0.y;  in34[4]=q0.z;  in34[5]=q0.w;
    in34[6]=q1.x;  in34[7]=q1.y;  in34[8]=q1.z;  in34[9]=q1.w;
    in34[10]=q2.x; in34[11]=q2.y; in34[12]=q2.z; in34[13]=q2.w;
    in34[14]=q3.x; in34[15]=q3.y; in34[16]=q3.z; in34[17]=q3.w;
    const float4* csrc = (const float4*)(g_feat0 + p*16);
    float4 a0 = csrc[0], a1 = csrc[1], a2 = csrc[2], a3 = csrc[3];
    float sad = fabsf(a0.x-q0.x)+fabsf(a0.y-q0.y)+fabsf(a0.z-q0.z)+fabsf(a0.w-q0.w)
              + fabsf(a1.x-q1.x)+fabsf(a1.y-q1.y)+fabsf(a1.z-q1.z)+fabsf(a1.w-q1.w)
              + fabsf(a2.x-q2.x)+fabsf(a2.y-q2.y)+fabsf(a2.z-q2.z)+fabsf(a2.w-q2.w)
              + fabsf(a3.x-q3.x)+fabsf(a3.y-q3.y)+fabsf(a3.z-q3.z)+fabsf(a3.w-q3.w);
    in34[1] = 2.0f * fexp(-sad * 0.0625f);

    // attentive pool FC: two op-half phases; weights from constant bank
#pragma unroll
    for (int h=0;h<2;h++){
        float acc[16];
#pragma unroll
        for (int o=0;o<16;o++) acc[o]=0.f;
#pragma unroll
        for (int cp=0;cp<17;cp++){
            float x0 = in34[2*cp], x1 = in34[2*cp+1];
#pragma unroll
            for (int o=0;o<16;o++){
                const float2 w = *(const float2*)&c_fc1[(h*16+o)*34 + 2*cp];
                acc[o] = fmaf(w.x, x0, acc[o]);
                acc[o] = fmaf(w.y, x1, acc[o]);
            }
        }
#pragma unroll
        for (int q=0;q<8;q++){
            u64 e2 = fexp2s(acc[2*q], acc[2*q+1]);
            u64 f2 = pk2(in34[2+h*16+2*q], in34[3+h*16+2*q]);
            ulonglong2 st; st.x = e2; st.y = mul2(e2, f2);
            s_red[pg][k][q] = st;
        }
        __syncwarp();
        if (k < 8){
            u64 es = 0ULL, ns = 0ULL;
#pragma unroll
            for (int k2=0;k2<16;k2++){
                ulonglong2 v = s_red[pg][k2][k];
                es = add2(es, v.x); ns = add2(ns, v.y);
            }
            float el,eh,nl,nh; upk2(el,eh,es); upk2(nl,nh,ns);
            s_flc[pg][h*8+k] = pk2(__fdividef(nl,el), __fdividef(nh,eh));
        }
        __syncwarp();
    }
    // p1m: lane k computes output channel k (packed over input pairs)
    u64 acc2 = 0ULL;
#pragma unroll
    for (int cp=0;cp<16;cp++) acc2 = fma2(s_p1mp[cp][k], s_flc[pg][cp], acc2);
    float al,ah; upk2(al,ah,acc2);
    g_feat1[p*16 + k] = fmaxf(fmaf(s_mg[k], al+ah, s_mb[k]), 0.0f);
}

// ================= Kernel C1: pool2 + p2m -> feat2 (32 ch) =================
__global__ __launch_bounds__(128) void kC1(const int* __restrict__ nidx,
                                           const float* __restrict__ mW,
                                           const float* __restrict__ mg,
                                           const float* __restrict__ mb){
    __shared__ u64 s_p2mp[16][32];
    __shared__ ulonglong2 s_red[8][16][9];
    __shared__ u64 s_flc[8][16];
    __shared__ float s_mg[32], s_mb[32];
    int tid = threadIdx.x;
    for (int i=tid; i<512; i+=128){ int cp=i>>5, o=i&31;
        s_p2mp[cp][o] = pk2(mW[o*32+2*cp], mW[o*32+2*cp+1]); }
    if (tid < 32){ s_mg[tid]=mg[tid]; s_mb[tid]=mb[tid]; }
    __syncthreads();

    int k = tid & 15, pg = tid >> 4;
    int p = blockIdx.x*8 + pg;
    int b = p / NN;
    int idx = nidx[p*KK + k];

    float in34[34];
    in34[0] = g_gdis[p*KK + k];
    const float4* fsrc = (const float4*)(g_feat1 + (b*NN + idx)*16);
    float4 q0 = fsrc[0], q1 = fsrc[1], q2 = fsrc[2], q3 = fsrc[3];
    in34[2]=q0.x;  in34[3]=q0.y;  in34[4]=q0.z;  in34[5]=q0.w;
    in34[6]=q1.x;  in34[7]=q1.y;  in34[8]=q1.z;  in34[9]=q1.w;
    in34[10]=q2.x; in34[11]=q2.y; in34[12]=q2.z; in34[13]=q2.w;
    in34[14]=q3.x; in34[15]=q3.y; in34[16]=q3.z; in34[17]=q3.w;
    const float4* csrc = (const float4*)(g_feat1 + p*16);
    float4 a0 = csrc[0], a1 = csrc[1], a2 = csrc[2], a3 = csrc[3];
    float sad = fabsf(a0.x-q0.x)+fabsf(a0.y-q0.y)+fabsf(a0.z-q0.z)+fabsf(a0.w-q0.w)
              + fabsf(a1.x-q1.x)+fabsf(a1.y-q1.y)+fabsf(a1.z-q1.z)+fabsf(a1.w-q1.w)
              + fabsf(a2.x-q2.x)+fabsf(a2.y-q2.y)+fabsf(a2.z-q2.z)+fabsf(a2.w-q2.w)
              + fabsf(a3.x-q3.x)+fabsf(a3.y-q3.y)+fabsf(a3.z-q3.z)+fabsf(a3.w-q3.w);
    in34[1] = 2.0f * fexp(-sad * 0.0625f);
    const float4* lsrc = (const float4*)(g_lrep2 + (p*KK + k)*16);
    float4 r0 = lsrc[0], r1 = lsrc[1], r2 = lsrc[2], r3 = lsrc[3];
    in34[18]=r0.x; in34[19]=r0.y; in34[20]=r0.z; in34[21]=r0.w;
    in34[22]=r1.x; in34[23]=r1.y; in34[24]=r1.z; in34[25]=r1.w;
    in34[26]=r2.x; in34[27]=r2.y; in34[28]=r2.z; in34[29]=r2.w;
    in34[30]=r3.x; in34[31]=r3.y; in34[32]=r3.z; in34[33]=r3.w;

#pragma unroll
    for (int h=0;h<2;h++){
        float acc[16];
#pragma unroll
        for (int o=0;o<16;o++) acc[o]=0.f;
#pragma unroll
        for (int cp=0;cp<17;cp++){
            float x0 = in34[2*cp], x1 = in34[2*cp+1];
#pragma unroll
            for (int o=0;o<16;o++){
                const float2 w = *(const float2*)&c_fc2[(h*16+o)*34 + 2*cp];
                acc[o] = fmaf(w.x, x0, acc[o]);
                acc[o] = fmaf(w.y, x1, acc[o]);
            }
        }
#pragma unroll
        for (int q=0;q<8;q++){
            u64 e2 = fexp2s(acc[2*q], acc[2*q+1]);
            u64 f2 = pk2(in34[2+h*16+2*q], in34[3+h*16+2*q]);
            ulonglong2 st; st.x = e2; st.y = mul2(e2, f2);
            s_red[pg][k][q] = st;
        }
        __syncwarp();
        if (k < 8){
            u64 es = 0ULL, ns = 0ULL;
#pragma unroll
            for (int k2=0;k2<16;k2++){
                ulonglong2 v = s_red[pg][k2][k];
                es = add2(es, v.x); ns = add2(ns, v.y);
            }
            float el,eh,nl,nh; upk2(el,eh,es); upk2(nl,nh,ns);
            s_flc[pg][h*8+k] = pk2(__fdividef(nl,el), __fdividef(nh,eh));
        }
        __syncwarp();
    }
    // p2m: lane k computes output channels 2k,2k+1 (packed over input pairs)
    u64 accA = 0ULL, accB = 0ULL;
#pragma unroll
    for (int cp=0;cp<16;cp++){
        ulonglong2 w = *reinterpret_cast<const ulonglong2*>(&s_p2mp[cp][2*k]);
        u64 f = s_flc[pg][cp];
        accA = fma2(w.x, f, accA);
        accB = fma2(w.y, f, accB);
    }
    float xl,xh,yl,yh; upk2(xl,xh,accA); upk2(yl,yh,accB);
    g_feat2[p*32 + 2*k]   = fmaxf(fmaf(s_mg[2*k],   xl+xh, s_mb[2*k]),   0.0f);
    g_feat2[p*32 + 2*k+1] = fmaxf(fmaf(s_mg[2*k+1], yl+yh, s_mb[2*k+1]), 0.0f);
}

// ============ Kernel C2: out = relu(A @ [feat2;feature;xyz;lg] + bias) ============
__global__ __launch_bounds__(256) void kC2(const float* __restrict__ feat,
                                           const float* __restrict__ xyz,
                                           float* __restrict__ out){
    __shared__ u64   s_Ap[52][32];
    __shared__ float s_X[52][68];
    __shared__ float s_bias[64];
    int tid = threadIdx.x;
    int p0 = blockIdx.x*64;
    int b = p0 / NN, n0 = p0 - b*NN;
    for (int i=tid; i<52*32; i+=256) s_Ap[i>>5][i&31] = g_Ap[i];
    if (tid < 64) s_bias[tid] = g_bias[tid];
    for (int i=tid; i<512; i+=256){
        float4 v = ((const float4*)g_feat2)[p0*8 + i];
        int pt = i>>3, c = (i&7)*4;
        s_X[c][pt]=v.x; s_X[c+1][pt]=v.y; s_X[c+2][pt]=v.z; s_X[c+3][pt]=v.w;
    }
    for (int i=tid; i<1024; i+=256){
        int row = i>>6, pt = i&63;
        s_X[32+row][pt] = feat[(b*16+row)*NN + n0 + pt];
    }
    for (int i=tid; i<192; i+=256){
        int pt = i/3, d = i - pt*3;
        s_X[48+d][pt] = xyz[(b*NN + n0 + pt)*3 + d];
    }
    for (int i=tid; i<64; i+=256) s_X[51][i] = g_lg[p0+i];
    __syncthreads();

    int i4 = tid >> 4;
    int j  = tid & 15;
    u64 acc[8];
#pragma unroll
    for (int t=0;t<8;t++) acc[t]=0ULL;
#pragma unroll
    for (int c=0;c<52;c++){
        ulonglong2 w = *reinterpret_cast<const ulonglong2*>(&s_Ap[c][2*i4]);
        float4 x = *reinterpret_cast<const float4*>(&s_X[c][4*j]);
        u64 d0=dup2(x.x), d1=dup2(x.y), d2=dup2(x.z), d3=dup2(x.w);
        acc[0]=fma2(w.x,d0,acc[0]); acc[1]=fma2(w.y,d0,acc[1]);
        acc[2]=fma2(w.x,d1,acc[2]); acc[3]=fma2(w.y,d1,acc[3]);
        acc[4]=fma2(w.x,d2,acc[4]); acc[5]=fma2(w.y,d2,acc[5]);
        acc[6]=fma2(w.x,d3,acc[6]); acc[7]=fma2(w.y,d3,acc[7]);
    }
    float r[4][4];
#pragma unroll
    for (int q=0;q<4;q++){
        upk2(r[q][0], r[q][1], acc[q*2]);
        upk2(r[q][2], r[q][3], acc[q*2+1]);
    }
#pragma unroll
    for (int oo=0;oo<4;oo++){
        int o = 4*i4 + oo;
        float bb = s_bias[o];
        float4 st = make_float4(
            fmaxf(r[0][oo]+bb, 0.f), fmaxf(r[1][oo]+bb, 0.f),
            fmaxf(r[2][oo]+bb, 0.f), fmaxf(r[3][oo]+bb, 0.f));
        *reinterpret_cast<float4*>(&out[(b*64+o)*NN + n0 + 4*j]) = st;
    }
}

extern "C" void kernel_launch(void* const* d_in, const int* in_sizes, int n_in,
                              void* d_out, int out_size){
    (void)in_sizes; (void)n_in; (void)out_size;
    const float* feature = (const float*)d_in[0];
    const float* xyz     = (const float*)d_in[1];
    const float* m1W  = (const float*)d_in[2];
    const float* m1g  = (const float*)d_in[3];
    const float* m1b  = (const float*)d_in[4];
    const float* lm1W = (const float*)d_in[5];
    const float* lm1g = (const float*)d_in[6];
    const float* lm1b = (const float*)d_in[7];
    const float* lm2W = (const float*)d_in[8];
    const float* lm2g = (const float*)d_in[9];
    const float* lm2b = (const float*)d_in[10];
    const float* p1fc = (const float*)d_in[11];
    const float* p1mW = (const float*)d_in[12];
    const float* p1mg = (const float*)d_in[13];
    const float* p1mb = (const float*)d_in[14];
    const float* p2fc = (const float*)d_in[15];
    const float* p2mW = (const float*)d_in[16];
    const float* p2mg = (const float*)d_in[17];
    const float* p2mb = (const float*)d_in[18];
    const float* m2W  = (const float*)d_in[19];
    const float* m2g  = (const float*)d_in[20];
    const float* m2b  = (const float*)d_in[21];
    const float* scW  = (const float*)d_in[22];
    const float* scg  = (const float*)d_in[23];
    const float* scb  = (const float*)d_in[24];
    const float* m3W  = (const float*)d_in[25];
    const float* m3g  = (const float*)d_in[26];
    const float* m3b  = (const float*)d_in[27];
    const float* m4W  = (const float*)d_in[28];
    const float* m4g  = (const float*)d_in[29];
    const float* m4b  = (const float*)d_in[30];
    const int*   nidx = (const int*)d_in[31];
    float* out = (float*)d_out;

    // Stage uniform weights into the constant bank (D2D async copies: graph-legal)
    cudaMemcpyToSymbolAsync(c_m1,  m1W,  256*4,  0, cudaMemcpyDeviceToDevice, 0);
    cudaMemcpyToSymbolAsync(c_m1g, m1g,  16*4,   0, cudaMemcpyDeviceToDevice, 0);
    cudaMemcpyToSymbolAsync(c_m1b, m1b,  16*4,   0, cudaMemcpyDeviceToDevice, 0);
    cudaMemcpyToSymbolAsync(c_lm1, lm1W, 144*4,  0, cudaMemcpyDeviceToDevice, 0);
    cudaMemcpyToSymbolAsync(c_lm1g,lm1g, 16*4,   0, cudaMemcpyDeviceToDevice, 0);
    cudaMemcpyToSymbolAsync(c_lm1b,lm1b, 16*4,   0, cudaMemcpyDeviceToDevice, 0);
    cudaMemcpyToSymbolAsync(c_lm2, lm2W, 256*4,  0, cudaMemcpyDeviceToDevice, 0);
    cudaMemcpyToSymbolAsync(c_lm2g,lm2g, 16*4,   0, cudaMemcpyDeviceToDevice, 0);
    cudaMemcpyToSymbolAsync(c_lm2b,lm2b, 16*4,   0, cudaMemcpyDeviceToDevice, 0);
    cudaMemcpyToSymbolAsync(c_fc1, p1fc, 1088*4, 0, cudaMemcpyDeviceToDevice, 0);
    cudaMemcpyToSymbolAsync(c_fc2, p2fc, 1088*4, 0, cudaMemcpyDeviceToDevice, 0);

    kPre<<<52, 64>>>(m2W,m2g,m2b, scW,scg,scb, m3W,m3g,m3b, m4W,m4g,m4b);
    kA  <<<NPTS/256, 256>>>(feature);
    kB  <<<NPTS/8, 128>>>(xyz, nidx, p1mW, p1mg, p1mb);
    kC1 <<<NPTS/8, 128>>>(nidx, p2mW, p2mg, p2mb);
    kC2 <<<NPTS/64, 256>>>(feature, xyz, out);
}

// round 6
// speedup vs baseline: 2.3944x; 1.1349x over previous
#include <cuda_runtime.h>
#include <math.h>

#define BB 4
#define NN 20480
#define KK 16
#define NPTS (BB*NN)

typedef unsigned long long u64;

// Scratch (static device globals — no allocation in kernel_launch)
__device__ __align__(16) float g_feat0[NPTS*16];
__device__ __align__(16) float g_feat1[NPTS*16];
__device__ __align__(16) float g_feat2[NPTS*32];
__device__ __align__(16) float g_lrep2[NPTS*KK*16];
__device__ __align__(16) float g_gdis[NPTS*KK];
__device__ __align__(16) float g_lg[NPTS];
__device__ __align__(16) float4 g_xyz4[NPTS];
__device__ __align__(16) u64   g_Ap[52*32];
__device__ __align__(16) float g_bias[64];
__device__ __align__(16) u64   g_stage[1416];   // packed-weight staging

// Packed (output-pair) weights in the constant bank
__constant__ u64 c_m1p[128];     // [c<16][op<8]
__constant__ u64 c_lm1p[72];     // [c<9][op<8]
__constant__ u64 c_lm2p[128];    // [c<16][op<8]
__constant__ u64 c_fc1p[544];    // [c<34][op<16]
__constant__ u64 c_fc2p[544];    // [c<34][op<16]
__constant__ float c_m1g[16],  c_m1b[16];
__constant__ float c_lm1g[16], c_lm1b[16];
__constant__ float c_lm2g[16], c_lm2b[16];

// ---------------- packed f32x2 helpers ----------------
__device__ __forceinline__ u64 pk2(float lo, float hi){
    u64 r; asm("mov.b64 %0,{%1,%2};" : "=l"(r) : "f"(lo), "f"(hi)); return r; }
__device__ __forceinline__ u64 dup2(float v){ return pk2(v,v); }
__device__ __forceinline__ void upk2(float& lo, float& hi, u64 v){
    asm("mov.b64 {%0,%1},%2;" : "=f"(lo), "=f"(hi) : "l"(v)); }
__device__ __forceinline__ u64 fma2(u64 a, u64 b, u64 c){
    u64 d; asm("fma.rn.f32x2 %0,%1,%2,%3;" : "=l"(d) : "l"(a),"l"(b),"l"(c)); return d; }
__device__ __forceinline__ u64 add2(u64 a, u64 b){
    u64 d; asm("add.rn.f32x2 %0,%1,%2;" : "=l"(d) : "l"(a),"l"(b)); return d; }
__device__ __forceinline__ u64 mul2(u64 a, u64 b){
    u64 d; asm("mul.rn.f32x2 %0,%1,%2;" : "=l"(d) : "l"(a),"l"(b)); return d; }
__device__ __forceinline__ u64 shx64(u64 v, int m){
    return __shfl_xor_sync(0xffffffffu, v, m);
}

// ---------- fast math on the FMA pipe ----------
__device__ __forceinline__ float fexp(float x){
    x = fminf(fmaxf(x, -80.0f), 80.0f);
    const float L2E = 1.4426950408889634f;
    float z  = fmaf(x, L2E, 12582912.0f);
    float nf = z - 12582912.0f;
    float f  = fmaf(x, L2E, -nf);
    float p  = fmaf(f, 1.3333558147e-3f, 9.6181291076e-3f);
    p = fmaf(f, p, 5.5504108664e-2f);
    p = fmaf(f, p, 2.4022650696e-1f);
    p = fmaf(f, p, 6.9314718056e-1f);
    p = fmaf(f, p, 1.0f);
    int e = (__float_as_int(z) << 23) + 0x3F800000;
    return p * __int_as_float(e);
}

__device__ __forceinline__ u64 fexp2s(float a, float b){
    a = fminf(fmaxf(a,-80.f),80.f)*1.4426950408889634f;
    b = fminf(fmaxf(b,-80.f),80.f)*1.4426950408889634f;
    float za = a + 12582912.f, zb = b + 12582912.f;
    float fa = a - (za - 12582912.f), fb = b - (zb - 12582912.f);
    u64 f2 = pk2(fa,fb);
    u64 p = fma2(f2, dup2(1.3333558147e-3f), dup2(9.6181291076e-3f));
    p = fma2(f2, p, dup2(5.5504108664e-2f));
    p = fma2(f2, p, dup2(2.4022650696e-1f));
    p = fma2(f2, p, dup2(6.9314718056e-1f));
    p = fma2(f2, p, dup2(1.0f));
    float sa = __int_as_float((__float_as_int(za)<<23)+0x3F800000);
    float sb = __int_as_float((__float_as_int(zb)<<23)+0x3F800000);
    return mul2(p, pk2(sa,sb));
}

__device__ __forceinline__ float fatan2(float y, float x){
    float ax = fabsf(x), ay = fabsf(y);
    float mx = fmaxf(ax, ay), mn = fminf(ax, ay);
    float a = (mx > 0.0f) ? __fdividef(mn, mx) : 0.0f;
    float s = a*a;
    float r = -0.0117212f;
    r = fmaf(r, s,  0.05265332f);
    r = fmaf(r, s, -0.11643287f);
    r = fmaf(r, s,  0.19354346f);
    r = fmaf(r, s, -0.33262347f);
    r = fmaf(r, s,  0.99997726f);
    r = r * a;
    if (ay > ax) r = 1.57079637f - r;
    if (x < 0.0f) r = 3.14159274f - r;
    if (y < 0.0f) r = -r;
    return r;
}

__device__ __forceinline__ float rsum16(float v){
    v += __shfl_xor_sync(0xffffffffu, v, 1);
    v += __shfl_xor_sync(0xffffffffu, v, 2);
    v += __shfl_xor_sync(0xffffffffu, v, 4);
    v += __shfl_xor_sync(0xffffffffu, v, 8);
    return v;
}
__device__ __forceinline__ float rmax16(float v){
    v = fmaxf(v, __shfl_xor_sync(0xffffffffu, v, 1));
    v = fmaxf(v, __shfl_xor_sync(0xffffffffu, v, 2));
    v = fmaxf(v, __shfl_xor_sync(0xffffffffu, v, 4));
    v = fmaxf(v, __shfl_xor_sync(0xffffffffu, v, 8));
    return v;
}

// Butterfly reduce 8 packed channel-pairs (e,nu) across a 16-lane segment.
// On exit every lane holds the full sums of value index
// idx(l) = 4*(l&1) + 2*((l>>1)&1) + ((l>>2)&1).
__device__ __forceinline__ void bfly16(const u64 e[8], const u64 nu[8], int lane,
                                       u64& eo, u64& no){
    bool u1 = lane & 1;
    u64 a[4], b[4];
#pragma unroll
    for (int i=0;i<4;i++){
        u64 ge = u1 ? e[i] : e[i+4];
        u64 gn = u1 ? nu[i] : nu[i+4];
        u64 re = shx64(ge,1), rn = shx64(gn,1);
        a[i] = add2(u1 ? e[i+4]  : e[i],  re);
        b[i] = add2(u1 ? nu[i+4] : nu[i], rn);
    }
    bool u2 = lane & 2;
    u64 c[2], d[2];
#pragma unroll
    for (int i=0;i<2;i++){
        u64 ge = u2 ? a[i] : a[i+2];
        u64 gn = u2 ? b[i] : b[i+2];
        u64 re = shx64(ge,2), rn = shx64(gn,2);
        c[i] = add2(u2 ? a[i+2] : a[i], re);
        d[i] = add2(u2 ? b[i+2] : b[i], rn);
    }
    bool u4 = lane & 4;
    {
        u64 ge = u4 ? c[0] : c[1];
        u64 gn = u4 ? d[0] : d[1];
        u64 re = shx64(ge,4), rn = shx64(gn,4);
        u64 ee = add2(u4 ? c[1] : c[0], re);
        u64 nn = add2(u4 ? d[1] : d[0], rn);
        eo = add2(ee, shx64(ee,8));
        no = add2(nn, shx64(nn,8));
    }
}

// === kPack: build packed-pair weight layouts into staging ===
__global__ void kPack(const float* __restrict__ m1W, const float* __restrict__ lm1W,
                      const float* __restrict__ lm2W, const float* __restrict__ fc1,
                      const float* __restrict__ fc2){
    int i = blockIdx.x*256 + threadIdx.x;
    if (i < 128){ int c=i>>3, op=i&7;
        g_stage[i] = pk2(m1W[2*op*16+c], m1W[(2*op+1)*16+c]); }
    else if (i < 200){ int j=i-128; int c=j/8, op=j%8;
        g_stage[i] = pk2(lm1W[2*op*9+c], lm1W[(2*op+1)*9+c]); }
    else if (i < 328){ int j=i-200; int c=j>>3, op=j&7;
        g_stage[i] = pk2(lm2W[2*op*16+c], lm2W[(2*op+1)*16+c]); }
    else if (i < 872){ int j=i-328; int c=j>>4, op=j&15;
        g_stage[i] = pk2(fc1[2*op*34+c], fc1[(2*op+1)*34+c]); }
    else if (i < 1416){ int j=i-872; int c=j>>4, op=j&15;
        g_stage[i] = pk2(fc2[2*op*34+c], fc2[(2*op+1)*34+c]); }
}

// =================== Kernel A: feat0 + xyz4 ===================
__global__ __launch_bounds__(256) void kA(const float* __restrict__ feat,
                                          const float* __restrict__ xyz){
    int tid = threadIdx.x;
    int p = blockIdx.x*256 + tid;
    int b = p / NN, n = p - b*NN;
    float x[16];
#pragma unroll
    for (int c=0;c<16;c++) x[c] = feat[(b*16 + c)*NN + n];
    u64 acc[8];
#pragma unroll
    for (int op=0;op<8;op++) acc[op]=0ULL;
#pragma unroll
    for (int c=0;c<16;c++){
        u64 xv = dup2(x[c]);
#pragma unroll
        for (int op=0;op<8;op++) acc[op] = fma2(c_m1p[c*8+op], xv, acc[op]);
    }
    float y[16];
#pragma unroll
    for (int op=0;op<8;op++){
        float lo,hi; upk2(lo,hi,acc[op]);
        y[2*op]   = fmaxf(fmaf(c_m1g[2*op],   lo, c_m1b[2*op]),   0.0f);
        y[2*op+1] = fmaxf(fmaf(c_m1g[2*op+1], hi, c_m1b[2*op+1]), 0.0f);
    }
    float4* dst = (float4*)(g_feat0 + p*16);
    dst[0] = make_float4(y[0],y[1],y[2],y[3]);
    dst[1] = make_float4(y[4],y[5],y[6],y[7]);
    dst[2] = make_float4(y[8],y[9],y[10],y[11]);
    dst[3] = make_float4(y[12],y[13],y[14],y[15]);
    g_xyz4[p] = make_float4(xyz[p*3+0], xyz[p*3+1], xyz[p*3+2], 0.0f);
}

// === kPre: fold m2/sc/m3/m4 into one A[52][64] + bias[64] ===
__global__ void kPre(const float* __restrict__ m2W, const float* __restrict__ m2g, const float* __restrict__ m2b,
                     const float* __restrict__ scW, const float* __restrict__ scg, const float* __restrict__ scb,
                     const float* __restrict__ m3W, const float* __restrict__ m3g, const float* __restrict__ m3b,
                     const float* __restrict__ m4W, const float* __restrict__ m4g, const float* __restrict__ m4b){
    __shared__ float row[64];
    int c = blockIdx.x, o = threadIdx.x;
    float acc = 0.f;
    if (c < 32){
        for (int j=0;j<64;j++) acc = fmaf(m4W[o*128+j]*m2g[j], m2W[j*32+c], acc);
    } else if (c < 48){
        int cc = c-32;
        for (int j=0;j<64;j++) acc = fmaf(m4W[o*128+j]*scg[j], scW[j*16+cc], acc);
    } else {
        int cc = c-48;
        for (int j=0;j<64;j++) acc = fmaf(m4W[o*128+64+j]*m3g[j], m3W[j*4+cc], acc);
    }
    row[o] = m4g[o]*acc;
    __syncthreads();
    if (o < 32) g_Ap[c*32+o] = pk2(row[2*o], row[2*o+1]);
    if (c == 0){
        float s = 0.f;
        for (int j=0;j<64;j++)
            s += m4W[o*128+j]*(m2b[j]+scb[j]) + m4W[o*128+64+j]*m3b[j];
        g_bias[o] = fmaf(m4g[o], s, m4b[o]);
    }
}

// =========== Kernel B: geometry + lrep + lrep2 + pool1 + p1m -> feat1 ===========
__global__ __launch_bounds__(128) void kB(const int* __restrict__ nidx,
                                          const float* __restrict__ mW,
                                          const float* __restrict__ mg,
                                          const float* __restrict__ mb){
    __shared__ u64 s_p1mp[16][16];
    __shared__ u64 s_flc[8][16];
    __shared__ float s_mg[16], s_mb[16];
    int tid = threadIdx.x;
    for (int i=tid; i<256; i+=128){ int cp=i>>4, o=i&15;
        s_p1mp[cp][o] = pk2(mW[o*32+2*cp], mW[o*32+2*cp+1]); }
    if (tid < 16){ s_mg[tid]=mg[tid]; s_mb[tid]=mb[tid]; }
    __syncthreads();

    int k = tid & 15, pg = tid >> 4;
    int p = blockIdx.x*8 + pg;
    int b = p / NN, n = p - b*NN;
    int idx = nidx[p*KK + k];
    float4 nb4 = g_xyz4[b*NN + idx];
    float4 c4  = g_xyz4[b*NN + n];
    float nx=nb4.x, ny=nb4.y, nz=nb4.z;
    float cx=c4.x,  cy=c4.y,  cz=c4.z;
    float rx = cx-nx, ry = cy-ny, rz = cz-nz;
    float dxy2 = fmaf(rx,rx, ry*ry);
    float rdis = sqrtf(dxy2 + rz*rz);
    float ralpha = fatan2(ry, rx);
    float rbeta  = fatan2(rz, sqrtf(dxy2));
    float mxn = rsum16(nx)*0.0625f;
    float myn = rsum16(ny)*0.0625f;
    float mzn = rsum16(nz)*0.0625f;
    float dx = cx - mxn, dy = cy - myn, dz = cz - mzn;
    float dalpha = fatan2(dy, dx);
    float dbeta  = fatan2(dz, sqrtf(fmaf(dx,dx,dy*dy)));
    float mr = rmax16(rdis);
    if (k == 0){
        float cn = sqrtf(cx*cx + cy*cy + cz*cz);
        g_lg[p] = __fdividef(mr*mr*mr, cn*cn*cn);
    }

    float lr[9] = { ralpha - dalpha, rbeta - dbeta, rdis, cx, cy, cz, nx, ny, nz };

    float in34[34];
    // lrep = relu(lm1) — packed fma2 from constant
    {
        u64 acc[8];
#pragma unroll
        for (int op=0;op<8;op++) acc[op]=0ULL;
#pragma unroll
        for (int c=0;c<9;c++){
            u64 xv = dup2(lr[c]);
#pragma unroll
            for (int op=0;op<8;op++) acc[op] = fma2(c_lm1p[c*8+op], xv, acc[op]);
        }
#pragma unroll
        for (int op=0;op<8;op++){
            float lo,hi; upk2(lo,hi,acc[op]);
            in34[18+2*op]   = fmaxf(fmaf(c_lm1g[2*op],   lo, c_lm1b[2*op]),   0.f);
            in34[18+2*op+1] = fmaxf(fmaf(c_lm1g[2*op+1], hi, c_lm1b[2*op+1]), 0.f);
        }
    }
    // lrep2 = relu(lm2 @ lrep)
    {
        u64 acc[8];
#pragma unroll
        for (int op=0;op<8;op++) acc[op]=0ULL;
#pragma unroll
        for (int c=0;c<16;c++){
            u64 xv = dup2(in34[18+c]);
#pragma unroll
            for (int op=0;op<8;op++) acc[op] = fma2(c_lm2p[c*8+op], xv, acc[op]);
        }
        float l2v[16];
#pragma unroll
        for (int op=0;op<8;op++){
            float lo,hi; upk2(lo,hi,acc[op]);
            l2v[2*op]   = fmaxf(fmaf(c_lm2g[2*op],   lo, c_lm2b[2*op]),   0.f);
            l2v[2*op+1] = fmaxf(fmaf(c_lm2g[2*op+1], hi, c_lm2b[2*op+1]), 0.f);
        }
        float4* ldst = (float4*)(g_lrep2 + (p*KK + k)*16);
        ldst[0] = make_float4(l2v[0],l2v[1],l2v[2],l2v[3]);
        ldst[1] = make_float4(l2v[4],l2v[5],l2v[6],l2v[7]);
        ldst[2] = make_float4(l2v[8],l2v[9],l2v[10],l2v[11]);
        ldst[3] = make_float4(l2v[12],l2v[13],l2v[14],l2v[15]);
    }

    // gather neighbor features + feature distance
    const float4* fsrc = (const float4*)(g_feat0 + (b*NN + idx)*16);
    float4 q0 = fsrc[0], q1 = fsrc[1], q2 = fsrc[2], q3 = fsrc[3];
    in34[2]=q0.x;  in34[3]=q0.y;  in34[4]=q0.z;  in34[5]=q0.w;
    in34[6]=q1.x;  in34[7]=q1.y;  in34[8]=q1.z;  in34[9]=q1.w;
    in34[10]=q2.x; in34[11]=q2.y; in34[12]=q2.z; in34[13]=q2.w;
    in34[14]=q3.x; in34[15]=q3.y; in34[16]=q3.z; in34[17]=q3.w;
    const float4* csrc = (const float4*)(g_feat0 + p*16);
    float4 a0 = csrc[0], a1 = csrc[1], a2 = csrc[2], a3 = csrc[3];
    float sad = fabsf(a0.x-q0.x)+fabsf(a0.y-q0.y)+fabsf(a0.z-q0.z)+fabsf(a0.w-q0.w)
              + fabsf(a1.x-q1.x)+fabsf(a1.y-q1.y)+fabsf(a1.z-q1.z)+fabsf(a1.w-q1.w)
              + fabsf(a2.x-q2.x)+fabsf(a2.y-q2.y)+fabsf(a2.z-q2.z)+fabsf(a2.w-q2.w)
              + fabsf(a3.x-q3.x)+fabsf(a3.y-q3.y)+fabsf(a3.z-q3.z)+fabsf(a3.w-q3.w);
    {
        u64 gf = fexp2s(-rdis, -sad*0.0625f);
        float gdis, fd; upk2(gdis, fd, gf);
        g_gdis[p*KK + k] = gdis;
        in34[0] = gdis;
        in34[1] = 2.0f*fd;
    }

    // attentive pool: 2 phases of 16 output channels; packed FC + butterfly reduce
#pragma unroll
    for (int h=0;h<2;h++){
        u64 acc[8];
#pragma unroll
        for (int q=0;q<8;q++) acc[q]=0ULL;
#pragma unroll
        for (int c=0;c<34;c++){
            u64 xv = dup2(in34[c]);
#pragma unroll
            for (int q=0;q<8;q++) acc[q] = fma2(c_fc1p[c*16 + h*8 + q], xv, acc[q]);
        }
        u64 e[8], nu[8];
#pragma unroll
        for (int q=0;q<8;q++){
            float lo,hi; upk2(lo,hi,acc[q]);
            e[q]  = fexp2s(lo,hi);
            nu[q] = mul2(e[q], pk2(in34[2+h*16+2*q], in34[3+h*16+2*q]));
        }
        u64 eo, no;
        bfly16(e, nu, k, eo, no);
        if (k < 8){
            int vidx = 4*(k&1) + 2*((k>>1)&1) + ((k>>2)&1);
            float el,eh,nl,nh; upk2(el,eh,eo); upk2(nl,nh,no);
            s_flc[pg][h*8+vidx] = pk2(__fdividef(nl,el), __fdividef(nh,eh));
        }
    }
    __syncwarp();
    // p1m: lane k computes output channel k
    u64 acc2 = 0ULL;
#pragma unroll
    for (int cp=0;cp<16;cp++) acc2 = fma2(s_p1mp[cp][k], s_flc[pg][cp], acc2);
    float al,ah; upk2(al,ah,acc2);
    g_feat1[p*16 + k] = fmaxf(fmaf(s_mg[k], al+ah, s_mb[k]), 0.0f);
}

// ================= Kernel C1: pool2 + p2m -> feat2 (32 ch) =================
__global__ __launch_bounds__(128) void kC1(const int* __restrict__ nidx,
                                           const float* __restrict__ mW,
                                           const float* __restrict__ mg,
                                           const float* __restrict__ mb){
    __shared__ u64 s_p2mp[16][32];
    __shared__ u64 s_flc[8][16];
    __shared__ float s_mg[32], s_mb[32];
    int tid = threadIdx.x;
    for (int i=tid; i<512; i+=128){ int cp=i>>5, o=i&31;
        s_p2mp[cp][o] = pk2(mW[o*32+2*cp], mW[o*32+2*cp+1]); }
    if (tid < 32){ s_mg[tid]=mg[tid]; s_mb[tid]=mb[tid]; }
    __syncthreads();

    int k = tid & 15, pg = tid >> 4;
    int p = blockIdx.x*8 + pg;
    int b = p / NN;
    int idx = nidx[p*KK + k];

    float in34[34];
    in34[0] = g_gdis[p*KK + k];
    const float4* fsrc = (const float4*)(g_feat1 + (b*NN + idx)*16);
    float4 q0 = fsrc[0], q1 = fsrc[1], q2 = fsrc[2], q3 = fsrc[3];
    in34[2]=q0.x;  in34[3]=q0.y;  in34[4]=q0.z;  in34[5]=q0.w;
    in34[6]=q1.x;  in34[7]=q1.y;  in34[8]=q1.z;  in34[9]=q1.w;
    in34[10]=q2.x; in34[11]=q2.y; in34[12]=q2.z; in34[13]=q2.w;
    in34[14]=q3.x; in34[15]=q3.y; in34[16]=q3.z; in34[17]=q3.w;
    const float4* csrc = (const float4*)(g_feat1 + p*16);
    float4 a0 = csrc[0], a1 = csrc[1], a2 = csrc[2], a3 = csrc[3];
    float sad = fabsf(a0.x-q0.x)+fabsf(a0.y-q0.y)+fabsf(a0.z-q0.z)+fabsf(a0.w-q0.w)
              + fabsf(a1.x-q1.x)+fabsf(a1.y-q1.y)+fabsf(a1.z-q1.z)+fabsf(a1.w-q1.w)
              + fabsf(a2.x-q2.x)+fabsf(a2.y-q2.y)+fabsf(a2.z-q2.z)+fabsf(a2.w-q2.w)
              + fabsf(a3.x-q3.x)+fabsf(a3.y-q3.y)+fabsf(a3.z-q3.z)+fabsf(a3.w-q3.w);
    in34[1] = 2.0f * fexp(-sad * 0.0625f);
    const float4* lsrc = (const float4*)(g_lrep2 + (p*KK + k)*16);
    float4 r0 = lsrc[0], r1 = lsrc[1], r2 = lsrc[2], r3 = lsrc[3];
    in34[18]=r0.x; in34[19]=r0.y; in34[20]=r0.z; in34[21]=r0.w;
    in34[22]=r1.x; in34[23]=r1.y; in34[24]=r1.z; in34[25]=r1.w;
    in34[26]=r2.x; in34[27]=r2.y; in34[28]=r2.z; in34[29]=r2.w;
    in34[30]=r3.x; in34[31]=r3.y; in34[32]=r3.z; in34[33]=r3.w;

#pragma unroll
    for (int h=0;h<2;h++){
        u64 acc[8];
#pragma unroll
        for (int q=0;q<8;q++) acc[q]=0ULL;
#pragma unroll
        for (int c=0;c<34;c++){
            u64 xv = dup2(in34[c]);
#pragma unroll
            for (int q=0;q<8;q++) acc[q] = fma2(c_fc2p[c*16 + h*8 + q], xv, acc[q]);
        }
        u64 e[8], nu[8];
#pragma unroll
        for (int q=0;q<8;q++){
            float lo,hi; upk2(lo,hi,acc[q]);
            e[q]  = fexp2s(lo,hi);
            nu[q] = mul2(e[q], pk2(in34[2+h*16+2*q], in34[3+h*16+2*q]));
        }
        u64 eo, no;
        bfly16(e, nu, k, eo, no);
        if (k < 8){
            int vidx = 4*(k&1) + 2*((k>>1)&1) + ((k>>2)&1);
            float el,eh,nl,nh; upk2(el,eh,eo); upk2(nl,nh,no);
            s_flc[pg][h*8+vidx] = pk2(__fdividef(nl,el), __fdividef(nh,eh));
        }
    }
    __syncwarp();
    // p2m: lane k computes output channels 2k,2k+1
    u64 accA = 0ULL, accB = 0ULL;
#pragma unroll
    for (int cp=0;cp<16;cp++){
        ulonglong2 w = *reinterpret_cast<const ulonglong2*>(&s_p2mp[cp][2*k]);
        u64 f = s_flc[pg][cp];
        accA = fma2(w.x, f, accA);
        accB = fma2(w.y, f, accB);
    }
    float xl,xh,yl,yh; upk2(xl,xh,accA); upk2(yl,yh,accB);
    g_feat2[p*32 + 2*k]   = fmaxf(fmaf(s_mg[2*k],   xl+xh, s_mb[2*k]),   0.0f);
    g_feat2[p*32 + 2*k+1] = fmaxf(fmaf(s_mg[2*k+1], yl+yh, s_mb[2*k+1]), 0.0f);
}

// ============ Kernel C2: out = relu(A @ [feat2;feature;xyz;lg] + bias) ============
__global__ __launch_bounds__(256) void kC2(const float* __restrict__ feat,
                                           const float* __restrict__ xyz,
                                           float* __restrict__ out){
    __shared__ u64   s_Ap[52][32];
    __shared__ float s_X[52][68];
    __shared__ float s_bias[64];
    int tid = threadIdx.x;
    int p0 = blockIdx.x*64;
    int b = p0 / NN, n0 = p0 - b*NN;
    for (int i=tid; i<52*32; i+=256) s_Ap[i>>5][i&31] = g_Ap[i];
    if (tid < 64) s_bias[tid] = g_bias[tid];
    for (int i=tid; i<512; i+=256){
        float4 v = ((const float4*)g_feat2)[p0*8 + i];
        int pt = i>>3, c = (i&7)*4;
        s_X[c][pt]=v.x; s_X[c+1][pt]=v.y; s_X[c+2][pt]=v.z; s_X[c+3][pt]=v.w;
    }
    for (int i=tid; i<1024; i+=256){
        int row = i>>6, pt = i&63;
        s_X[32+row][pt] = feat[(b*16+row)*NN + n0 + pt];
    }
    for (int i=tid; i<192; i+=256){
        int pt = i/3, d = i - pt*3;
        s_X[48+d][pt] = xyz[(b*NN + n0 + pt)*3 + d];
    }
    for (int i=tid; i<64; i+=256) s_X[51][i] = g_lg[p0+i];
    __syncthreads();

    int i4 = tid >> 4;
    int j  = tid & 15;
    u64 acc[8];
#pragma unroll
    for (int t=0;t<8;t++) acc[t]=0ULL;
#pragma unroll
    for (int c=0;c<52;c++){
        ulonglong2 w = *reinterpret_cast<const ulonglong2*>(&s_Ap[c][2*i4]);
        float4 x = *reinterpret_cast<const float4*>(&s_X[c][4*j]);
        u64 d0=dup2(x.x), d1=dup2(x.y), d2=dup2(x.z), d3=dup2(x.w);
        acc[0]=fma2(w.x,d0,acc[0]); acc[1]=fma2(w.y,d0,acc[1]);
        acc[2]=fma2(w.x,d1,acc[2]); acc[3]=fma2(w.y,d1,acc[3]);
        acc[4]=fma2(w.x,d2,acc[4]); acc[5]=fma2(w.y,d2,acc[5]);
        acc[6]=fma2(w.x,d3,acc[6]); acc[7]=fma2(w.y,d3,acc[7]);
    }
    float r[4][4];
#pragma unroll
    for (int q=0;q<4;q++){
        upk2(r[q][0], r[q][1], acc[q*2]);
        upk2(r[q][2], r[q][3], acc[q*2+1]);
    }
#pragma unroll
    for (int oo=0;oo<4;oo++){
        int o = 4*i4 + oo;
        float bb = s_bias[o];
        float4 st = make_float4(
            fmaxf(r[0][oo]+bb, 0.f), fmaxf(r[1][oo]+bb, 0.f),
            fmaxf(r[2][oo]+bb, 0.f), fmaxf(r[3][oo]+bb, 0.f));
        *reinterpret_cast<float4*>(&out[(b*64+o)*NN + n0 + 4*j]) = st;
    }
}

extern "C" void kernel_launch(void* const* d_in, const int* in_sizes, int n_in,
                              void* d_out, int out_size){
    (void)in_sizes; (void)n_in; (void)out_size;
    const float* feature = (const float*)d_in[0];
    const float* xyz     = (const float*)d_in[1];
    const float* m1W  = (const float*)d_in[2];
    const float* m1g  = (const float*)d_in[3];
    const float* m1b  = (const float*)d_in[4];
    const float* lm1W = (const float*)d_in[5];
    const float* lm1g = (const float*)d_in[6];
    const float* lm1b = (const float*)d_in[7];
    const float* lm2W = (const float*)d_in[8];
    const float* lm2g = (const float*)d_in[9];
    const float* lm2b = (const float*)d_in[10];
    const float* p1fc = (const float*)d_in[11];
    const float* p1mW = (const float*)d_in[12];
    const float* p1mg = (const float*)d_in[13];
    const float* p1mb = (const float*)d_in[14];
    const float* p2fc = (const float*)d_in[15];
    const float* p2mW = (const float*)d_in[16];
    const float* p2mg = (const float*)d_in[17];
    const float* p2mb = (const float*)d_in[18];
    const float* m2W  = (const float*)d_in[19];
    const float* m2g  = (const float*)d_in[20];
    const float* m2b  = (const float*)d_in[21];
    const float* scW  = (const float*)d_in[22];
    const float* scg  = (const float*)d_in[23];
    const float* scb  = (const float*)d_in[24];
    const float* m3W  = (const float*)d_in[25];
    const float* m3g  = (const float*)d_in[26];
    const float* m3b  = (const float*)d_in[27];
    const float* m4W  = (const float*)d_in[28];
    const float* m4g  = (const float*)d_in[29];
    const float* m4b  = (const float*)d_in[30];
    const int*   nidx = (const int*)d_in[31];
    float* out = (float*)d_out;

    // Build packed weights in staging, then D2D into the constant bank
    kPack<<<6, 256>>>(m1W, lm1W, lm2W, p1fc, p2fc);
    void* stagePtr = nullptr;
    cudaGetSymbolAddress(&stagePtr, g_stage);
    const u64* st = (const u64*)stagePtr;
    cudaMemcpyToSymbolAsync(c_m1p,  st+0,   128*8, 0, cudaMemcpyDeviceToDevice, 0);
    cudaMemcpyToSymbolAsync(c_lm1p, st+128, 72*8,  0, cudaMemcpyDeviceToDevice, 0);
    cudaMemcpyToSymbolAsync(c_lm2p, st+200, 128*8, 0, cudaMemcpyDeviceToDevice, 0);
    cudaMemcpyToSymbolAsync(c_fc1p, st+328, 544*8, 0, cudaMemcpyDeviceToDevice, 0);
    cudaMemcpyToSymbolAsync(c_fc2p, st+872, 544*8, 0, cudaMemcpyDeviceToDevice, 0);
    cudaMemcpyToSymbolAsync(c_m1g,  m1g,  16*4, 0, cudaMemcpyDeviceToDevice, 0);
    cudaMemcpyToSymbolAsync(c_m1b,  m1b,  16*4, 0, cudaMemcpyDeviceToDevice, 0);
    cudaMemcpyToSymbolAsync(c_lm1g, lm1g, 16*4, 0, cudaMemcpyDeviceToDevice, 0);
    cudaMemcpyToSymbolAsync(c_lm1b, lm1b, 16*4, 0, cudaMemcpyDeviceToDevice, 0);
    cudaMemcpyToSymbolAsync(c_lm2g, lm2g, 16*4, 0, cudaMemcpyDeviceToDevice, 0);
    cudaMemcpyToSymbolAsync(c_lm2b, lm2b, 16*4, 0, cudaMemcpyDeviceToDevice, 0);

    kPre<<<52, 64>>>(m2W,m2g,m2b, scW,scg,scb, m3W,m3g,m3b, m4W,m4g,m4b);
    kA  <<<NPTS/256, 256>>>(feature, xyz);
    kB  <<<NPTS/8, 128>>>(nidx, p1mW, p1mg, p1mb);
    kC1 <<<NPTS/8, 128>>>(nidx, p2mW, p2mg, p2mb);
    kC2 <<<NPTS/64, 256>>>(feature, xyz, out);
}